// round 3
// baseline (speedup 1.0000x reference)
#include <cuda_runtime.h>
#include <cuda_bf16.h>
#include <mma.h>
#include <cstdint>

using namespace nvcuda;

// Problem constants (shapes fixed by the reference)
#define NNODES 15360       // 512 graphs * 30 nodes
#define HID 64
#define EMAX 41984         // 2 * 512 * 41
#define NLAYERS 5
#define QCOLS 2112         // 32*64 (w-part) + 64 (b2-part)
#define KS 192             // split-bf16 K (hi|hi|lo vs hi|lo|hi)
#define APAD 208           // padded smem K stride (bf16 elems)

// ---------------- scratch (device globals; no allocation allowed) -----------
__device__ float g_h0[NNODES * HID];
__device__ float g_h1[NNODES * HID];
__device__ float g_Q[(size_t)NNODES * QCOLS];       // ~130 MB
__device__ float g_z[EMAX * 32];
__device__ float g_agg[NNODES * HID];
__device__ float g_deg[NNODES];
__device__ float g_invdeg[NNODES];
__device__ __nv_bfloat16 g_hs[(size_t)NNODES * KS];            // A' [m][192]
__device__ __nv_bfloat16 g_Ws[(size_t)NLAYERS * QCOLS * KS];   // B' [l][n][192]

// ---------------- split prep kernels ----------------------------------------
// B'[l][n][0:64]=hi(W2p), [64:128]=lo, [128:192]=hi ; W2p[k][n] mapping as before
__global__ void k_wsplit(const float* __restrict__ W2, const float* __restrict__ b2,
                         __nv_bfloat16* __restrict__ Ws) {
    int idx = blockIdx.x * blockDim.x + threadIdx.x;
    const int total = NLAYERS * QCOLS * HID;
    if (idx >= total) return;
    int k = idx & 63;
    int n = (idx >> 6) % QCOLS;
    int l = idx / (QCOLS * HID);
    float v;
    if (n < 2048) {
        int j = n >> 6, o = n & 63;
        v = W2[(size_t)(l * 32 + j) * 4096 + k * 64 + o];
    } else {
        v = b2[(size_t)l * 4096 + k * 64 + (n - 2048)];
    }
    __nv_bfloat16 hi = __float2bfloat16(v);
    __nv_bfloat16 lo = __float2bfloat16(v - __bfloat162float(hi));
    __nv_bfloat16* r = Ws + ((size_t)l * QCOLS + n) * KS;
    r[k] = hi;
    r[64 + k] = lo;
    r[128 + k] = hi;
}

// A'[m][0:64]=hi(h), [64:128]=hi, [128:192]=lo
__global__ void k_hsplit(const float* __restrict__ h, __nv_bfloat16* __restrict__ hs, int n) {
    int i = blockIdx.x * blockDim.x + threadIdx.x;
    if (i >= n) return;
    float v = h[i];
    __nv_bfloat16 hi = __float2bfloat16(v);
    __nv_bfloat16 lo = __float2bfloat16(v - __bfloat162float(hi));
    int node = i >> 6, k = i & 63;
    __nv_bfloat16* r = hs + (size_t)node * KS;
    r[k] = hi;
    r[64 + k] = hi;
    r[128 + k] = lo;
}

// ---------------- WMMA bf16 GEMM: Q = A'(15360x192) @ B'^T(192x2112) ---------
// block tile 128(M) x 96(N), 8 warps (4m x 2n), warp tile 32x48.
__global__ __launch_bounds__(256) void k_qwmma(const __nv_bfloat16* __restrict__ A,
                                               const __nv_bfloat16* __restrict__ B,
                                               float* __restrict__ Q) {
    extern __shared__ __nv_bfloat16 sm[];
    __nv_bfloat16* As = sm;                 // 128 x APAD
    __nv_bfloat16* Bs = sm + 128 * APAD;    // 96 x APAD
    const int m0 = blockIdx.y * 128;
    const int n0 = blockIdx.x * 96;
    const int t = threadIdx.x;

    // stage A tile: 128 rows x 192 bf16 (24 uint4/row)
    for (int i = t; i < 128 * 24; i += 256) {
        int r = i / 24, c = (i % 24) * 8;
        *(uint4*)(As + r * APAD + c) = *(const uint4*)(A + (size_t)(m0 + r) * KS + c);
    }
    // stage B tile: 96 rows x 192 bf16
    for (int i = t; i < 96 * 24; i += 256) {
        int r = i / 24, c = (i % 24) * 8;
        *(uint4*)(Bs + r * APAD + c) = *(const uint4*)(B + (size_t)(n0 + r) * KS + c);
    }
    __syncthreads();

    const int w = t >> 5;
    const int mw = (w & 3) * 32;   // warp m offset within tile
    const int nw = (w >> 2) * 48;  // warp n offset within tile

    wmma::fragment<wmma::accumulator, 16, 16, 16, float> acc[2][3];
#pragma unroll
    for (int i = 0; i < 2; i++)
#pragma unroll
        for (int j = 0; j < 3; j++) wmma::fill_fragment(acc[i][j], 0.f);

#pragma unroll
    for (int k = 0; k < KS; k += 16) {
        wmma::fragment<wmma::matrix_a, 16, 16, 16, __nv_bfloat16, wmma::row_major> af[2];
        wmma::fragment<wmma::matrix_b, 16, 16, 16, __nv_bfloat16, wmma::col_major> bf[3];
#pragma unroll
        for (int i = 0; i < 2; i++)
            wmma::load_matrix_sync(af[i], As + (mw + i * 16) * APAD + k, APAD);
#pragma unroll
        for (int j = 0; j < 3; j++)
            wmma::load_matrix_sync(bf[j], Bs + (nw + j * 16) * APAD + k, APAD);
#pragma unroll
        for (int i = 0; i < 2; i++)
#pragma unroll
            for (int j = 0; j < 3; j++)
                wmma::mma_sync(acc[i][j], af[i], bf[j], acc[i][j]);
    }
#pragma unroll
    for (int i = 0; i < 2; i++)
#pragma unroll
        for (int j = 0; j < 3; j++)
            wmma::store_matrix_sync(Q + (size_t)(m0 + mw + i * 16) * QCOLS + n0 + nw + j * 16,
                                    acc[i][j], QCOLS, wmma::mem_row_major);
}

// ---------------- small utility kernels --------------------------------------
__global__ void k_zero(float* p, int n) {
    int i = blockIdx.x * blockDim.x + threadIdx.x;
    if (i < n) p[i] = 0.f;
}

// h0 = x @ Wp + bp   (x: [N,8], Wp: [8,64])
__global__ void k_proj(const float* __restrict__ x, const float* __restrict__ Wp,
                       const float* __restrict__ bp, float* __restrict__ h, int N) {
    int t = blockIdx.x * blockDim.x + threadIdx.x;
    if (t >= N * HID) return;
    int n = t >> 6, c = t & 63;
    const float* xr = x + n * 8;
    float acc = bp[c];
#pragma unroll
    for (int k = 0; k < 8; k++) acc += xr[k] * Wp[k * 64 + c];
    h[t] = acc;
}

__global__ void k_deg(const int* __restrict__ dst, float* __restrict__ deg, int E) {
    int e = blockIdx.x * blockDim.x + threadIdx.x;
    if (e < E) atomicAdd(&deg[dst[e]], 1.0f);
}

__global__ void k_invdeg(const float* __restrict__ deg, float* __restrict__ inv, int N) {
    int n = blockIdx.x * blockDim.x + threadIdx.x;
    if (n < N) inv[n] = 1.0f / fmaxf(deg[n], 1.0f);
}

// z[e,j] = relu(b1[j] + [h[src]|h[dst]] . W1[:,j]);  one warp per edge, lane = j
__global__ void k_z(const float* __restrict__ h, const int* __restrict__ src,
                    const int* __restrict__ dst, const float* __restrict__ W1l,
                    const float* __restrict__ b1l, float* __restrict__ z, int E) {
    __shared__ float W1s[128 * 32];
    for (int i = threadIdx.x; i < 128 * 32; i += blockDim.x) W1s[i] = W1l[i];
    __syncthreads();
    int e = (blockIdx.x * blockDim.x + threadIdx.x) >> 5;
    int lane = threadIdx.x & 31;
    if (e >= E) return;
    int s = src[e], d = dst[e];
    const float* hs = h + s * 64;
    const float* hd = h + d * 64;
    float acc = b1l[lane];
#pragma unroll
    for (int k = 0; k < 64; k++) acc += hs[k] * W1s[k * 32 + lane];
#pragma unroll
    for (int k = 0; k < 64; k++) acc += hd[k] * W1s[(64 + k) * 32 + lane];
    z[e * 32 + lane] = fmaxf(acc, 0.f);
}

// msg[e,:] = Qb[src] + z[e,:] @ Qw[src];  scatter-add into agg[dst]
__global__ void k_msg(const float* __restrict__ Q, const float* __restrict__ z,
                      const int* __restrict__ src, const int* __restrict__ dst,
                      float* __restrict__ agg, int E) {
    int e = (blockIdx.x * blockDim.x + threadIdx.x) >> 5;
    int lane = threadIdx.x & 31;
    if (e >= E) return;
    int s = src[e], d = dst[e];
    const float2* Qs = (const float2*)(Q + (size_t)s * QCOLS);
    float zj = z[e * 32 + lane];
    float2 m = Qs[1024 + lane];  // bias part (float offset 2048)
#pragma unroll
    for (int j = 0; j < 32; j++) {
        float zz = __shfl_sync(0xffffffffu, zj, j);
        float2 q = Qs[j * 32 + lane];
        m.x += zz * q.x;
        m.y += zz * q.y;
    }
    float* ad = agg + (size_t)d * 64 + 2 * lane;
    atomicAdd(ad, m.x);
    atomicAdd(ad + 1, m.y);
}

// h_out = relu( BN( agg/deg + h@Wr + br ) ) + h
__global__ void k_node(const float* __restrict__ hin, const float* __restrict__ agg,
                       const float* __restrict__ invdeg, const float* __restrict__ Wr,
                       const float* __restrict__ br, const float* __restrict__ gamma,
                       const float* __restrict__ beta, const float* __restrict__ rmean,
                       const float* __restrict__ rvar, float* __restrict__ hout, int N) {
    int t = blockIdx.x * blockDim.x + threadIdx.x;
    if (t >= N * HID) return;
    int n = t >> 6, c = t & 63;
    const float* hr = hin + (size_t)n * 64;
    float acc = br[c];
#pragma unroll
    for (int k = 0; k < 64; k++) acc += hr[k] * Wr[k * 64 + c];
    float h2 = agg[t] * invdeg[n] + acc;
    float scale = gamma[c] * rsqrtf(rvar[c] + 1e-5f);
    h2 = (h2 - rmean[c]) * scale + beta[c];
    hout[t] = fmaxf(h2, 0.f) + hr[c];
}

// out[i] = relu([h[u]|h[v]] @ Wm1 + bm1) @ Wm2 + bm2 ; one warp per output row
__global__ void k_final(const float* __restrict__ h, const int* __restrict__ bu,
                        const int* __restrict__ bv, const float* __restrict__ Wm1,
                        const float* __restrict__ bm1, const float* __restrict__ Wm2,
                        const float* __restrict__ bm2, float* __restrict__ out,
                        int nout, int B, int npg) {
    int i = (blockIdx.x * blockDim.x + threadIdx.x) >> 5;
    int lane = threadIdx.x & 31;
    if (i >= nout) return;
    int g = i / B, b = i - g * B;
    int u = bu[b] + g * npg;
    int v = bv[b] + g * npg;
    const float* hu = h + (size_t)u * 64;
    const float* hv = h + (size_t)v * 64;
    float a0 = bm1[lane], a1 = bm1[lane + 32];
#pragma unroll
    for (int k = 0; k < 64; k++) {
        float x0 = hu[k];
        a0 += x0 * Wm1[k * 64 + lane];
        a1 += x0 * Wm1[k * 64 + lane + 32];
    }
#pragma unroll
    for (int k = 0; k < 64; k++) {
        float x1 = hv[k];
        a0 += x1 * Wm1[(64 + k) * 64 + lane];
        a1 += x1 * Wm1[(64 + k) * 64 + lane + 32];
    }
    float r = fmaxf(a0, 0.f) * Wm2[lane] + fmaxf(a1, 0.f) * Wm2[lane + 32];
#pragma unroll
    for (int off = 16; off; off >>= 1) r += __shfl_down_sync(0xffffffffu, r, off);
    if (lane == 0) out[i] = r + bm2[0];
}

extern "C" void kernel_launch(void* const* d_in, const int* in_sizes, int n_in,
                              void* d_out, int out_size) {
    const float* x   = (const float*)d_in[0];
    const int* eidx  = (const int*)d_in[1];
    const int* bu    = (const int*)d_in[2];
    const int* bv    = (const int*)d_in[3];
    int base = (in_sizes[4] == 1) ? 5 : 4;
    const float* Wp    = (const float*)d_in[base + 0];
    const float* bp    = (const float*)d_in[base + 1];
    const float* W1    = (const float*)d_in[base + 2];
    const float* b1    = (const float*)d_in[base + 3];
    const float* W2    = (const float*)d_in[base + 4];
    const float* b2    = (const float*)d_in[base + 5];
    const float* Wr    = (const float*)d_in[base + 6];
    const float* br    = (const float*)d_in[base + 7];
    const float* gamma = (const float*)d_in[base + 8];
    const float* beta  = (const float*)d_in[base + 9];
    const float* rmean = (const float*)d_in[base + 10];
    const float* rvar  = (const float*)d_in[base + 11];
    const float* Wm1   = (const float*)d_in[base + 12];
    const float* bm1   = (const float*)d_in[base + 13];
    const float* Wm2   = (const float*)d_in[base + 14];
    const float* bm2   = (const float*)d_in[base + 15];

    const int Nn = in_sizes[0] / 8;     // 15360
    const int E  = in_sizes[1] / 2;     // 41984
    const int B  = in_sizes[2];         // 41
    const int G  = out_size / B;        // 512
    const int npg = Nn / G;             // 30
    const int* src = eidx;
    const int* dst = eidx + E;

    static float *p_h0 = nullptr, *p_h1, *p_Q, *p_z, *p_agg, *p_deg, *p_invdeg;
    static __nv_bfloat16 *p_hs, *p_Ws;
    static const int SMEMB = (128 + 96) * APAD * sizeof(__nv_bfloat16);
    if (!p_h0) {
        cudaGetSymbolAddress((void**)&p_h0, g_h0);
        cudaGetSymbolAddress((void**)&p_h1, g_h1);
        cudaGetSymbolAddress((void**)&p_Q, g_Q);
        cudaGetSymbolAddress((void**)&p_z, g_z);
        cudaGetSymbolAddress((void**)&p_agg, g_agg);
        cudaGetSymbolAddress((void**)&p_deg, g_deg);
        cudaGetSymbolAddress((void**)&p_invdeg, g_invdeg);
        cudaGetSymbolAddress((void**)&p_hs, g_hs);
        cudaGetSymbolAddress((void**)&p_Ws, g_Ws);
        cudaFuncSetAttribute(k_qwmma, cudaFuncAttributeMaxDynamicSharedMemorySize, SMEMB);
    }

    // prep
    k_wsplit<<<(NLAYERS * QCOLS * HID + 255) / 256, 256>>>(W2, b2, p_Ws);
    k_zero<<<(Nn + 255) / 256, 256>>>(p_deg, Nn);
    k_proj<<<(Nn * HID + 255) / 256, 256>>>(x, Wp, bp, p_h0, Nn);
    k_deg<<<(E + 255) / 256, 256>>>(dst, p_deg, E);
    k_invdeg<<<(Nn + 255) / 256, 256>>>(p_deg, p_invdeg, Nn);

    float* cur = p_h0;
    float* nxt = p_h1;
    for (int l = 0; l < NLAYERS; l++) {
        k_zero<<<(Nn * HID + 255) / 256, 256>>>(p_agg, Nn * HID);
        k_z<<<(E + 3) / 4, 128>>>(cur, src, dst, W1 + (size_t)l * 128 * 32,
                                  b1 + (size_t)l * 32, p_z, E);
        k_hsplit<<<(Nn * HID + 255) / 256, 256>>>(cur, p_hs, Nn * HID);
        dim3 gq(QCOLS / 96, Nn / 128);
        k_qwmma<<<gq, 256, SMEMB>>>(p_hs, p_Ws + (size_t)l * QCOLS * KS, p_Q);
        k_msg<<<(E + 7) / 8, 256>>>(p_Q, p_z, src, dst, p_agg, E);
        k_node<<<(Nn * HID + 255) / 256, 256>>>(
            cur, p_agg, p_invdeg, Wr + (size_t)l * 64 * 64, br + (size_t)l * 64,
            gamma + (size_t)l * 64, beta + (size_t)l * 64, rmean + (size_t)l * 64,
            rvar + (size_t)l * 64, nxt, Nn);
        float* tmp = cur; cur = nxt; nxt = tmp;
    }
    k_final<<<(out_size + 7) / 8, 256>>>(cur, bu, bv, Wm1, bm1, Wm2, bm2,
                                         (float*)d_out, out_size, B, npg);
}

// round 4
// speedup vs baseline: 1.1088x; 1.1088x over previous
#include <cuda_runtime.h>
#include <cuda_bf16.h>
#include <mma.h>
#include <cstdint>

using namespace nvcuda;

// Problem constants (shapes fixed by the reference)
#define NNODES 15360       // 512 graphs * 30 nodes
#define HID 64
#define NPG 30             // nodes per graph
#define NBR 41             // branches per graph
#define NEPG 82            // edges per graph (bidirectional)
#define NLAYERS 5
#define QCOLS 2112         // 32*64 (w-part) + 64 (b2-part)
#define KS 192             // split-bf16 K (hi|hi|lo vs hi|lo|hi)
#define APAD 208           // padded smem K stride (bf16 elems)
#define BN_EPS 1e-5f

// ---------------- scratch (device globals; no allocation allowed) -----------
__device__ float g_h0[NNODES * HID];
__device__ float g_h1[NNODES * HID];
__device__ float g_Q[(size_t)NNODES * QCOLS];       // ~130 MB
__device__ __nv_bfloat16 g_hs[(size_t)NNODES * KS];            // A' [m][192]
__device__ __nv_bfloat16 g_Ws[(size_t)NLAYERS * QCOLS * KS];   // B' [l][n][192]

// ---------------- split prep kernels ----------------------------------------
// B'[l][n][0:64]=hi(W2p), [64:128]=lo, [128:192]=hi
__global__ void k_wsplit(const float* __restrict__ W2, const float* __restrict__ b2,
                         __nv_bfloat16* __restrict__ Ws) {
    int idx = blockIdx.x * blockDim.x + threadIdx.x;
    const int total = NLAYERS * QCOLS * HID;
    if (idx >= total) return;
    int k = idx & 63;
    int n = (idx >> 6) % QCOLS;
    int l = idx / (QCOLS * HID);
    float v;
    if (n < 2048) {
        int j = n >> 6, o = n & 63;
        v = W2[(size_t)(l * 32 + j) * 4096 + k * 64 + o];
    } else {
        v = b2[(size_t)l * 4096 + k * 64 + (n - 2048)];
    }
    __nv_bfloat16 hi = __float2bfloat16(v);
    __nv_bfloat16 lo = __float2bfloat16(v - __bfloat162float(hi));
    __nv_bfloat16* r = Ws + ((size_t)l * QCOLS + n) * KS;
    r[k] = hi;
    r[64 + k] = lo;
    r[128 + k] = hi;
}

__device__ __forceinline__ void write_split(__nv_bfloat16* hs, int node, int k, float v) {
    __nv_bfloat16 hi = __float2bfloat16(v);
    __nv_bfloat16 lo = __float2bfloat16(v - __bfloat162float(hi));
    __nv_bfloat16* r = hs + (size_t)node * KS;
    r[k] = hi;
    r[64 + k] = hi;
    r[128 + k] = lo;
}

// h0 = x @ Wp + bp  (+ bf16 split of h0)
__global__ void k_proj(const float* __restrict__ x, const float* __restrict__ Wp,
                       const float* __restrict__ bp, float* __restrict__ h,
                       __nv_bfloat16* __restrict__ hs, int N) {
    int t = blockIdx.x * blockDim.x + threadIdx.x;
    if (t >= N * HID) return;
    int n = t >> 6, c = t & 63;
    const float* xr = x + n * 8;
    float acc = bp[c];
#pragma unroll
    for (int k = 0; k < 8; k++) acc += xr[k] * Wp[k * 64 + c];
    h[t] = acc;
    write_split(hs, n, c, acc);
}

// ---------------- WMMA bf16 GEMM: Q = A'(15360x192) @ B'^T(192x2112) ---------
// block tile 128(M) x 96(N), 8 warps (4m x 2n), warp tile 32x48.
__global__ __launch_bounds__(256) void k_qwmma(const __nv_bfloat16* __restrict__ A,
                                               const __nv_bfloat16* __restrict__ B,
                                               float* __restrict__ Q) {
    extern __shared__ __nv_bfloat16 sm[];
    __nv_bfloat16* As = sm;                 // 128 x APAD
    __nv_bfloat16* Bs = sm + 128 * APAD;    // 96 x APAD
    const int m0 = blockIdx.y * 128;
    const int n0 = blockIdx.x * 96;
    const int t = threadIdx.x;

    for (int i = t; i < 128 * 24; i += 256) {
        int r = i / 24, c = (i % 24) * 8;
        *(uint4*)(As + r * APAD + c) = *(const uint4*)(A + (size_t)(m0 + r) * KS + c);
    }
    for (int i = t; i < 96 * 24; i += 256) {
        int r = i / 24, c = (i % 24) * 8;
        *(uint4*)(Bs + r * APAD + c) = *(const uint4*)(B + (size_t)(n0 + r) * KS + c);
    }
    __syncthreads();

    const int w = t >> 5;
    const int mw = (w & 3) * 32;
    const int nw = (w >> 2) * 48;

    wmma::fragment<wmma::accumulator, 16, 16, 16, float> acc[2][3];
#pragma unroll
    for (int i = 0; i < 2; i++)
#pragma unroll
        for (int j = 0; j < 3; j++) wmma::fill_fragment(acc[i][j], 0.f);

#pragma unroll
    for (int k = 0; k < KS; k += 16) {
        wmma::fragment<wmma::matrix_a, 16, 16, 16, __nv_bfloat16, wmma::row_major> af[2];
        wmma::fragment<wmma::matrix_b, 16, 16, 16, __nv_bfloat16, wmma::col_major> bf[3];
#pragma unroll
        for (int i = 0; i < 2; i++)
            wmma::load_matrix_sync(af[i], As + (mw + i * 16) * APAD + k, APAD);
#pragma unroll
        for (int j = 0; j < 3; j++)
            wmma::load_matrix_sync(bf[j], Bs + (nw + j * 16) * APAD + k, APAD);
#pragma unroll
        for (int i = 0; i < 2; i++)
#pragma unroll
            for (int j = 0; j < 3; j++)
                wmma::mma_sync(acc[i][j], af[i], bf[j], acc[i][j]);
    }
#pragma unroll
    for (int i = 0; i < 2; i++)
#pragma unroll
        for (int j = 0; j < 3; j++)
            wmma::store_matrix_sync(Q + (size_t)(m0 + mw + i * 16) * QCOLS + n0 + nw + j * 16,
                                    acc[i][j], QCOLS, wmma::mem_row_major);
}

// ---------------- fused per-graph layer kernel --------------------------------
// one block per graph: z (edge MLP) -> msg via Q gather -> smem scatter-mean ->
// root GEMM + BN + relu + residual -> h' (+ bf16 split)
__global__ __launch_bounds__(256) void k_fused(
    const float* __restrict__ h, const int* __restrict__ src, const int* __restrict__ dst,
    const float* __restrict__ Q, const float* __restrict__ W1l, const float* __restrict__ b1l,
    const float* __restrict__ Wr, const float* __restrict__ br,
    const float* __restrict__ gamma, const float* __restrict__ beta,
    const float* __restrict__ rmean, const float* __restrict__ rvar,
    float* __restrict__ hout, __nv_bfloat16* __restrict__ hs, int E2) {
    __shared__ float sh[NPG * HID];        // 7.5 KB
    __shared__ float sW[128 * 32];         // 16 KB (W1, later reused for Wr)
    __shared__ float sz[NEPG * 32];        // 10.25 KB
    __shared__ float sagg[NPG * HID];      // 7.5 KB
    __shared__ float sdeg[NPG];
    __shared__ int sse[NEPG], sde[NEPG];

    const int g = blockIdx.x;
    const int tid = threadIdx.x;
    const int w = tid >> 5;
    const int lane = tid & 31;
    const int nbase = g * NPG;

    for (int i = tid; i < NPG * HID; i += 256) {
        sh[i] = h[nbase * HID + i];
        sagg[i] = 0.f;
    }
    for (int i = tid; i < 128 * 32; i += 256) sW[i] = W1l[i];
    if (tid < NPG) sdeg[tid] = 0.f;
    __syncthreads();

    // --- z + deg; warp per edge ---
    float b1v = b1l[lane];
    for (int k = w; k < NEPG; k += 8) {
        int ei = (k < NBR) ? g * NBR + k : E2 + g * NBR + (k - NBR);
        int s = src[ei] - nbase;
        int d = dst[ei] - nbase;
        if (lane == 0) { sse[k] = s; sde[k] = d; atomicAdd(&sdeg[d], 1.0f); }
        const float* hsrow = sh + s * 64;
        const float* hdrow = sh + d * 64;
        float acc = b1v;
#pragma unroll
        for (int kk = 0; kk < 64; kk++) acc += hsrow[kk] * sW[kk * 32 + lane];
#pragma unroll
        for (int kk = 0; kk < 64; kk++) acc += hdrow[kk] * sW[(64 + kk) * 32 + lane];
        sz[k * 32 + lane] = fmaxf(acc, 0.f);
    }
    __syncthreads();

    // --- msg: warp per edge, gather Q[src], smem scatter ---
    for (int k = w; k < NEPG; k += 8) {
        int s = sse[k], d = sde[k];
        const float2* Qs = (const float2*)(Q + (size_t)(nbase + s) * QCOLS);
        float zj = sz[k * 32 + lane];
        float2 m = Qs[1024 + lane];  // bias part
#pragma unroll
        for (int j = 0; j < 32; j++) {
            float zz = __shfl_sync(0xffffffffu, zj, j);
            float2 q = Qs[j * 32 + lane];
            m.x += zz * q.x;
            m.y += zz * q.y;
        }
        atomicAdd(&sagg[d * 64 + 2 * lane], m.x);
        atomicAdd(&sagg[d * 64 + 2 * lane + 1], m.y);
    }
    __syncthreads();

    // --- reload sW with Wr ---
    for (int i = tid; i < 64 * 64; i += 256) sW[i] = Wr[i];
    __syncthreads();

    // --- node update ---
    for (int i = tid; i < NPG * HID; i += 256) {
        int n = i >> 6, c = i & 63;
        const float* hr = sh + n * 64;
        float acc = br[c];
#pragma unroll
        for (int kk = 0; kk < 64; kk++) acc += hr[kk] * sW[kk * 64 + c];
        float h2 = sagg[i] / fmaxf(sdeg[n], 1.0f) + acc;
        float scale = gamma[c] * rsqrtf(rvar[c] + BN_EPS);
        h2 = (h2 - rmean[c]) * scale + beta[c];
        float r = fmaxf(h2, 0.f) + sh[i];
        hout[nbase * HID + i] = r;
        write_split(hs, nbase + n, c, r);
    }
}

// out[i] = relu([h[u]|h[v]] @ Wm1 + bm1) @ Wm2 + bm2 ; one warp per output row
__global__ void k_final(const float* __restrict__ h, const int* __restrict__ bu,
                        const int* __restrict__ bv, const float* __restrict__ Wm1,
                        const float* __restrict__ bm1, const float* __restrict__ Wm2,
                        const float* __restrict__ bm2, float* __restrict__ out,
                        int nout, int B, int npg) {
    int i = (blockIdx.x * blockDim.x + threadIdx.x) >> 5;
    int lane = threadIdx.x & 31;
    if (i >= nout) return;
    int g = i / B, b = i - g * B;
    int u = bu[b] + g * npg;
    int v = bv[b] + g * npg;
    const float* hu = h + (size_t)u * 64;
    const float* hv = h + (size_t)v * 64;
    float a0 = bm1[lane], a1 = bm1[lane + 32];
#pragma unroll
    for (int k = 0; k < 64; k++) {
        float x0 = hu[k];
        a0 += x0 * Wm1[k * 64 + lane];
        a1 += x0 * Wm1[k * 64 + lane + 32];
    }
#pragma unroll
    for (int k = 0; k < 64; k++) {
        float x1 = hv[k];
        a0 += x1 * Wm1[(64 + k) * 64 + lane];
        a1 += x1 * Wm1[(64 + k) * 64 + lane + 32];
    }
    float r = fmaxf(a0, 0.f) * Wm2[lane] + fmaxf(a1, 0.f) * Wm2[lane + 32];
#pragma unroll
    for (int off = 16; off; off >>= 1) r += __shfl_down_sync(0xffffffffu, r, off);
    if (lane == 0) out[i] = r + bm2[0];
}

extern "C" void kernel_launch(void* const* d_in, const int* in_sizes, int n_in,
                              void* d_out, int out_size) {
    const float* x   = (const float*)d_in[0];
    const int* eidx  = (const int*)d_in[1];
    const int* bu    = (const int*)d_in[2];
    const int* bv    = (const int*)d_in[3];
    int base = (in_sizes[4] == 1) ? 5 : 4;
    const float* Wp    = (const float*)d_in[base + 0];
    const float* bp    = (const float*)d_in[base + 1];
    const float* W1    = (const float*)d_in[base + 2];
    const float* b1    = (const float*)d_in[base + 3];
    const float* W2    = (const float*)d_in[base + 4];
    const float* b2    = (const float*)d_in[base + 5];
    const float* Wr    = (const float*)d_in[base + 6];
    const float* br    = (const float*)d_in[base + 7];
    const float* gamma = (const float*)d_in[base + 8];
    const float* beta  = (const float*)d_in[base + 9];
    const float* rmean = (const float*)d_in[base + 10];
    const float* rvar  = (const float*)d_in[base + 11];
    const float* Wm1   = (const float*)d_in[base + 12];
    const float* bm1   = (const float*)d_in[base + 13];
    const float* Wm2   = (const float*)d_in[base + 14];
    const float* bm2   = (const float*)d_in[base + 15];

    const int Nn = in_sizes[0] / 8;     // 15360
    const int E  = in_sizes[1] / 2;     // 41984
    const int B  = in_sizes[2];         // 41
    const int G  = out_size / B;        // 512
    const int npg = Nn / G;             // 30
    const int* src = eidx;
    const int* dst = eidx + E;
    const int E2 = E / 2;

    static float *p_h0 = nullptr, *p_h1, *p_Q;
    static __nv_bfloat16 *p_hs, *p_Ws;
    static const int SMEMB = (128 + 96) * APAD * sizeof(__nv_bfloat16);
    if (!p_h0) {
        cudaGetSymbolAddress((void**)&p_h0, g_h0);
        cudaGetSymbolAddress((void**)&p_h1, g_h1);
        cudaGetSymbolAddress((void**)&p_Q, g_Q);
        cudaGetSymbolAddress((void**)&p_hs, g_hs);
        cudaGetSymbolAddress((void**)&p_Ws, g_Ws);
        cudaFuncSetAttribute(k_qwmma, cudaFuncAttributeMaxDynamicSharedMemorySize, SMEMB);
    }

    // prep (launches 1,2)
    k_wsplit<<<(NLAYERS * QCOLS * HID + 255) / 256, 256>>>(W2, b2, p_Ws);
    k_proj<<<(Nn * HID + 255) / 256, 256>>>(x, Wp, bp, p_h0, p_hs, Nn);

    float* cur = p_h0;
    float* nxt = p_h1;
    dim3 gq(QCOLS / 96, Nn / 128);
    for (int l = 0; l < NLAYERS; l++) {
        k_qwmma<<<gq, 256, SMEMB>>>(p_hs, p_Ws + (size_t)l * QCOLS * KS, p_Q);
        k_fused<<<G, 256>>>(cur, src, dst, p_Q,
                            W1 + (size_t)l * 128 * 32, b1 + (size_t)l * 32,
                            Wr + (size_t)l * 64 * 64, br + (size_t)l * 64,
                            gamma + (size_t)l * 64, beta + (size_t)l * 64,
                            rmean + (size_t)l * 64, rvar + (size_t)l * 64,
                            nxt, p_hs, E2);
        float* tmp = cur; cur = nxt; nxt = tmp;
    }
    k_final<<<(out_size + 7) / 8, 256>>>(cur, bu, bv, Wm1, bm1, Wm2, bm2,
                                         (float*)d_out, out_size, B, npg);
}

// round 6
// speedup vs baseline: 1.2561x; 1.1328x over previous
#include <cuda_runtime.h>
#include <cuda_bf16.h>
#include <cuda_fp16.h>
#include <mma.h>
#include <cstdint>

using namespace nvcuda;

// Problem constants (shapes fixed by the reference)
#define NNODES 15360       // 512 graphs * 30 nodes
#define HID 64
#define NPG 30             // nodes per graph
#define NBR 41             // branches per graph
#define NEPG 82            // edges per graph (bidirectional)
#define NLAYERS 5
#define QCOLS 2112         // 32*64 (w-part) + 64 (b2-part)
#define KS 192             // split-bf16 K (hi|hi|lo vs hi|lo|hi)
#define APAD 208           // padded smem K stride (bf16 elems)
#define BN_EPS 1e-5f

// ---------------- scratch (device globals; no allocation allowed) -----------
__device__ float g_h0[NNODES * HID];
__device__ float g_h1[NNODES * HID];
__device__ __half g_Q[(size_t)NNODES * QCOLS];       // ~65 MB, fp16
__device__ __nv_bfloat16 g_hs[(size_t)NNODES * KS];            // A' [m][192]
__device__ __nv_bfloat16 g_Ws[(size_t)NLAYERS * QCOLS * KS];   // B' [l][n][192]

// ---------------- split prep kernels ----------------------------------------
// B'[l][n][0:64]=hi(W2p), [64:128]=lo, [128:192]=hi  (processed in [lo,hi) range)
__global__ void k_wsplit(const float* __restrict__ W2, const float* __restrict__ b2,
                         __nv_bfloat16* __restrict__ Ws, int lo0, int hi0) {
    int idx = lo0 + blockIdx.x * blockDim.x + threadIdx.x;
    if (idx >= hi0) return;
    int k = idx & 63;
    int n = (idx >> 6) % QCOLS;
    int l = idx / (QCOLS * HID);
    float v;
    if (n < 2048) {
        int j = n >> 6, o = n & 63;
        v = W2[(size_t)(l * 32 + j) * 4096 + k * 64 + o];
    } else {
        v = b2[(size_t)l * 4096 + k * 64 + (n - 2048)];
    }
    __nv_bfloat16 hi = __float2bfloat16(v);
    __nv_bfloat16 lo = __float2bfloat16(v - __bfloat162float(hi));
    __nv_bfloat16* r = Ws + ((size_t)l * QCOLS + n) * KS;
    r[k] = hi;
    r[64 + k] = lo;
    r[128 + k] = hi;
}

__device__ __forceinline__ void write_split(__nv_bfloat16* hs, int node, int k, float v) {
    __nv_bfloat16 hi = __float2bfloat16(v);
    __nv_bfloat16 lo = __float2bfloat16(v - __bfloat162float(hi));
    __nv_bfloat16* r = hs + (size_t)node * KS;
    r[k] = hi;
    r[64 + k] = hi;
    r[128 + k] = lo;
}

// h0 = x @ Wp + bp  (+ bf16 split of h0)
__global__ void k_proj(const float* __restrict__ x, const float* __restrict__ Wp,
                       const float* __restrict__ bp, float* __restrict__ h,
                       __nv_bfloat16* __restrict__ hs, int N) {
    int t = blockIdx.x * blockDim.x + threadIdx.x;
    if (t >= N * HID) return;
    int n = t >> 6, c = t & 63;
    const float* xr = x + n * 8;
    float acc = bp[c];
#pragma unroll
    for (int k = 0; k < 8; k++) acc += xr[k] * Wp[k * 64 + c];
    h[t] = acc;
    write_split(hs, n, c, acc);
}

// ---------------- WMMA bf16 GEMM: Q = A'(15360x192) @ B'^T(192x2112), fp16 out
// block tile 128(M) x 96(N), 8 warps (4m x 2n), warp tile 32x48.
__global__ __launch_bounds__(256) void k_qwmma(const __nv_bfloat16* __restrict__ A,
                                               const __nv_bfloat16* __restrict__ B,
                                               __half* __restrict__ Q) {
    extern __shared__ __nv_bfloat16 sm[];
    __nv_bfloat16* As = sm;                 // 128 x APAD
    __nv_bfloat16* Bs = sm + 128 * APAD;    // 96 x APAD
    const int m0 = blockIdx.y * 128;
    const int n0 = blockIdx.x * 96;
    const int t = threadIdx.x;

    for (int i = t; i < 128 * 24; i += 256) {
        int r = i / 24, c = (i % 24) * 8;
        *(uint4*)(As + r * APAD + c) = *(const uint4*)(A + (size_t)(m0 + r) * KS + c);
    }
    for (int i = t; i < 96 * 24; i += 256) {
        int r = i / 24, c = (i % 24) * 8;
        *(uint4*)(Bs + r * APAD + c) = *(const uint4*)(B + (size_t)(n0 + r) * KS + c);
    }
    __syncthreads();

    const int w = t >> 5;
    const int lane = t & 31;
    const int mw = (w & 3) * 32;
    const int nw = (w >> 2) * 48;

    wmma::fragment<wmma::accumulator, 16, 16, 16, float> acc[2][3];
#pragma unroll
    for (int i = 0; i < 2; i++)
#pragma unroll
        for (int j = 0; j < 3; j++) wmma::fill_fragment(acc[i][j], 0.f);

#pragma unroll
    for (int k = 0; k < KS; k += 16) {
        wmma::fragment<wmma::matrix_a, 16, 16, 16, __nv_bfloat16, wmma::row_major> af[2];
        wmma::fragment<wmma::matrix_b, 16, 16, 16, __nv_bfloat16, wmma::col_major> bf[3];
#pragma unroll
        for (int i = 0; i < 2; i++)
            wmma::load_matrix_sync(af[i], As + (mw + i * 16) * APAD + k, APAD);
#pragma unroll
        for (int j = 0; j < 3; j++)
            wmma::load_matrix_sync(bf[j], Bs + (nw + j * 16) * APAD + k, APAD);
#pragma unroll
        for (int i = 0; i < 2; i++)
#pragma unroll
            for (int j = 0; j < 3; j++)
                wmma::mma_sync(acc[i][j], af[i], bf[j], acc[i][j]);
    }

    // epilogue: stage fp32 tile per warp (stride 20 floats = 80B, mult of 16B),
    // convert to fp16, vectorized store
    __syncthreads();
    float* stage = (float*)sm + w * 320;  // 16x20 floats per warp
#pragma unroll
    for (int i = 0; i < 2; i++) {
#pragma unroll
        for (int j = 0; j < 3; j++) {
            wmma::store_matrix_sync(stage, acc[i][j], 20, wmma::mem_row_major);
            __syncwarp();
            int r = lane >> 1, c0 = (lane & 1) * 8;
            const float* sr = stage + r * 20 + c0;
            half2 hv[4];
#pragma unroll
            for (int q = 0; q < 4; q++)
                hv[q] = __floats2half2_rn(sr[2 * q], sr[2 * q + 1]);
            *(uint4*)(Q + (size_t)(m0 + mw + i * 16 + r) * QCOLS + n0 + nw + j * 16 + c0) =
                *(uint4*)hv;
            __syncwarp();
        }
    }
}

// ---------------- fused per-graph layer kernel --------------------------------
__global__ __launch_bounds__(256) void k_fused(
    const float* __restrict__ h, const int* __restrict__ src, const int* __restrict__ dst,
    const __half* __restrict__ Qh, const float* __restrict__ W1l, const float* __restrict__ b1l,
    const float* __restrict__ Wr, const float* __restrict__ br,
    const float* __restrict__ gamma, const float* __restrict__ beta,
    const float* __restrict__ rmean, const float* __restrict__ rvar,
    float* __restrict__ hout, __nv_bfloat16* __restrict__ hs, int E2) {
    __shared__ float sh[NPG * HID];        // 7.5 KB
    __shared__ float sW[128 * 32];         // 16 KB (W1, later reused for Wr)
    __shared__ float sz[NEPG * 32];        // 10.25 KB
    __shared__ float sagg[NPG * HID];      // 7.5 KB
    __shared__ float sdeg[NPG];
    __shared__ int sse[NEPG], sde[NEPG];

    const int g = blockIdx.x;
    const int tid = threadIdx.x;
    const int w = tid >> 5;
    const int lane = tid & 31;
    const int nbase = g * NPG;

    for (int i = tid; i < NPG * HID; i += 256) {
        sh[i] = h[nbase * HID + i];
        sagg[i] = 0.f;
    }
    for (int i = tid; i < 128 * 32; i += 256) sW[i] = W1l[i];
    if (tid < NPG) sdeg[tid] = 0.f;
    __syncthreads();

    // --- z + deg; warp per edge ---
    float b1v = b1l[lane];
    for (int k = w; k < NEPG; k += 8) {
        int ei = (k < NBR) ? g * NBR + k : E2 + g * NBR + (k - NBR);
        int s = src[ei] - nbase;
        int d = dst[ei] - nbase;
        if (lane == 0) { sse[k] = s; sde[k] = d; atomicAdd(&sdeg[d], 1.0f); }
        const float* hsrow = sh + s * 64;
        const float* hdrow = sh + d * 64;
        float acc = b1v;
#pragma unroll
        for (int kk = 0; kk < 64; kk++) acc += hsrow[kk] * sW[kk * 32 + lane];
#pragma unroll
        for (int kk = 0; kk < 64; kk++) acc += hdrow[kk] * sW[(64 + kk) * 32 + lane];
        sz[k * 32 + lane] = fmaxf(acc, 0.f);
    }
    __syncthreads();

    // --- msg: warp per edge; lane = (j-offset, o-chunk); uint4 fp16 loads ---
    const int c = lane & 7;    // o-chunk: outputs c*8 .. c*8+7
    const int jo = lane >> 3;  // j offset within group of 4
    for (int k = w; k < NEPG; k += 8) {
        int s = sse[k], d = sde[k];
        const __half* Qs = Qh + (size_t)(nbase + s) * QCOLS;
        float zval = sz[k * 32 + lane];
        float acc[8];
#pragma unroll
        for (int i = 0; i < 8; i++) acc[i] = 0.f;
#pragma unroll
        for (int j0 = 0; j0 < 8; j0++) {
            int j = j0 * 4 + jo;
            float zz = __shfl_sync(0xffffffffu, zval, j);
            uint4 qv = *(const uint4*)(Qs + j * 64 + c * 8);
            const half2* qh = (const half2*)&qv;
#pragma unroll
            for (int i = 0; i < 4; i++) {
                float2 f = __half22float2(qh[i]);
                acc[2 * i] += zz * f.x;
                acc[2 * i + 1] += zz * f.y;
            }
        }
#pragma unroll
        for (int i = 0; i < 8; i++) {
            acc[i] += __shfl_xor_sync(0xffffffffu, acc[i], 8);
            acc[i] += __shfl_xor_sync(0xffffffffu, acc[i], 16);
        }
        int o = c * 8 + jo * 2;
        float2 bias = __half22float2(*(const half2*)(Qs + 2048 + o));
        atomicAdd(&sagg[d * 64 + o], acc[jo * 2] + bias.x);
        atomicAdd(&sagg[d * 64 + o + 1], acc[jo * 2 + 1] + bias.y);
    }
    __syncthreads();

    // --- reload sW with Wr ---
    for (int i = tid; i < 64 * 64; i += 256) sW[i] = Wr[i];
    __syncthreads();

    // --- node update ---
    for (int i = tid; i < NPG * HID; i += 256) {
        int n = i >> 6, cc = i & 63;
        const float* hr = sh + n * 64;
        float acc = br[cc];
#pragma unroll
        for (int kk = 0; kk < 64; kk++) acc += hr[kk] * sW[kk * 64 + cc];
        float h2 = sagg[i] / fmaxf(sdeg[n], 1.0f) + acc;
        float scale = gamma[cc] * rsqrtf(rvar[cc] + BN_EPS);
        h2 = (h2 - rmean[cc]) * scale + beta[cc];
        float r = fmaxf(h2, 0.f) + sh[i];
        hout[nbase * HID + i] = r;
        write_split(hs, nbase + n, cc, r);
    }
}

// out[i] = relu([h[u]|h[v]] @ Wm1 + bm1) @ Wm2 + bm2 ; one warp per output row
__global__ void k_final(const float* __restrict__ h, const int* __restrict__ bu,
                        const int* __restrict__ bv, const float* __restrict__ Wm1,
                        const float* __restrict__ bm1, const float* __restrict__ Wm2,
                        const float* __restrict__ bm2, float* __restrict__ out,
                        int nout, int B, int npg) {
    int i = (blockIdx.x * blockDim.x + threadIdx.x) >> 5;
    int lane = threadIdx.x & 31;
    if (i >= nout) return;
    int g = i / B, b = i - g * B;
    int u = bu[b] + g * npg;
    int v = bv[b] + g * npg;
    const float* hu = h + (size_t)u * 64;
    const float* hv = h + (size_t)v * 64;
    float a0 = bm1[lane], a1 = bm1[lane + 32];
#pragma unroll
    for (int k = 0; k < 64; k++) {
        float x0 = hu[k];
        a0 += x0 * Wm1[k * 64 + lane];
        a1 += x0 * Wm1[k * 64 + lane + 32];
    }
#pragma unroll
    for (int k = 0; k < 64; k++) {
        float x1 = hv[k];
        a0 += x1 * Wm1[(64 + k) * 64 + lane];
        a1 += x1 * Wm1[(64 + k) * 64 + lane + 32];
    }
    float r = fmaxf(a0, 0.f) * Wm2[lane] + fmaxf(a1, 0.f) * Wm2[lane + 32];
#pragma unroll
    for (int off = 16; off; off >>= 1) r += __shfl_down_sync(0xffffffffu, r, off);
    if (lane == 0) out[i] = r + bm2[0];
}

extern "C" void kernel_launch(void* const* d_in, const int* in_sizes, int n_in,
                              void* d_out, int out_size) {
    const float* x   = (const float*)d_in[0];
    const int* eidx  = (const int*)d_in[1];
    const int* bu    = (const int*)d_in[2];
    const int* bv    = (const int*)d_in[3];
    int base = (in_sizes[4] == 1) ? 5 : 4;
    const float* Wp    = (const float*)d_in[base + 0];
    const float* bp    = (const float*)d_in[base + 1];
    const float* W1    = (const float*)d_in[base + 2];
    const float* b1    = (const float*)d_in[base + 3];
    const float* W2    = (const float*)d_in[base + 4];
    const float* b2    = (const float*)d_in[base + 5];
    const float* Wr    = (const float*)d_in[base + 6];
    const float* br    = (const float*)d_in[base + 7];
    const float* gamma = (const float*)d_in[base + 8];
    const float* beta  = (const float*)d_in[base + 9];
    const float* rmean = (const float*)d_in[base + 10];
    const float* rvar  = (const float*)d_in[base + 11];
    const float* Wm1   = (const float*)d_in[base + 12];
    const float* bm1   = (const float*)d_in[base + 13];
    const float* Wm2   = (const float*)d_in[base + 14];
    const float* bm2   = (const float*)d_in[base + 15];

    const int Nn = in_sizes[0] / 8;     // 15360
    const int E  = in_sizes[1] / 2;     // 41984
    const int B  = in_sizes[2];         // 41
    const int G  = out_size / B;        // 512
    const int npg = Nn / G;             // 30
    const int* src = eidx;
    const int* dst = eidx + E;
    const int E2 = E / 2;

    static float *p_h0 = nullptr, *p_h1;
    static __half* p_Q;
    static __nv_bfloat16 *p_hs, *p_Ws;
    static const int SMEMB = (128 + 96) * APAD * sizeof(__nv_bfloat16);
    if (!p_h0) {
        cudaGetSymbolAddress((void**)&p_h0, g_h0);
        cudaGetSymbolAddress((void**)&p_h1, g_h1);
        cudaGetSymbolAddress((void**)&p_Q, g_Q);
        cudaGetSymbolAddress((void**)&p_hs, g_hs);
        cudaGetSymbolAddress((void**)&p_Ws, g_Ws);
        cudaFuncSetAttribute(k_qwmma, cudaFuncAttributeMaxDynamicSharedMemorySize, SMEMB);
    }

    // prep — ordered so launch index 5 is k_qwmma (layer 1) for ncu -s 5
    const int WTOT = NLAYERS * QCOLS * HID;
    k_proj<<<(Nn * HID + 255) / 256, 256>>>(x, Wp, bp, p_h0, p_hs, Nn);
    k_wsplit<<<(WTOT / 2 + 255) / 256, 256>>>(W2, b2, p_Ws, 0, WTOT / 2);
    k_wsplit<<<(WTOT / 2 + 255) / 256, 256>>>(W2, b2, p_Ws, WTOT / 2, WTOT);

    float* cur = p_h0;
    float* nxt = p_h1;
    dim3 gq(QCOLS / 96, Nn / 128);
    for (int l = 0; l < NLAYERS; l++) {
        k_qwmma<<<gq, 256, SMEMB>>>(p_hs, p_Ws + (size_t)l * QCOLS * KS, p_Q);
        k_fused<<<G, 256>>>(cur, src, dst, p_Q,
                            W1 + (size_t)l * 128 * 32, b1 + (size_t)l * 32,
                            Wr + (size_t)l * 64 * 64, br + (size_t)l * 64,
                            gamma + (size_t)l * 64, beta + (size_t)l * 64,
                            rmean + (size_t)l * 64, rvar + (size_t)l * 64,
                            nxt, p_hs, E2);
        float* tmp = cur; cur = nxt; nxt = tmp;
    }
    k_final<<<(out_size + 7) / 8, 256>>>(cur, bu, bv, Wm1, bm1, Wm2, bm2,
                                         (float*)d_out, out_size, B, npg);
}

// round 7
// speedup vs baseline: 1.7275x; 1.3754x over previous
#include <cuda_runtime.h>
#include <cuda_fp16.h>
#include <mma.h>
#include <cstdint>

using namespace nvcuda;

// Problem constants (shapes fixed by the reference)
#define NNODES 15360       // 512 graphs * 30 nodes
#define HID 64
#define NPG 30             // nodes per graph
#define NBR 41             // branches per graph
#define NEPG 82            // edges per graph (bidirectional)
#define NLAYERS 5
#define QCOLS 2112         // 32*64 (w-part) + 64 (b2-part)
#define KA 128             // A' k-extent: [h_hi | h_lo] fp16
#define APAD 136           // padded smem stride for A (halfs)
#define BPAD 72            // padded smem stride for B (halfs)
#define BN_EPS 1e-5f

// ---------------- scratch (device globals; no allocation allowed) -----------
__device__ float g_h0[NNODES * HID];
__device__ float g_h1[NNODES * HID];
__device__ __half g_Q[(size_t)NNODES * QCOLS];              // ~65 MB fp16
__device__ __half g_hs[(size_t)NNODES * KA];                // A' [m][128]
__device__ __half g_Ws[(size_t)NLAYERS * QCOLS * HID];      // B  [l][n][64] fp16

// ---------------- split prep kernels ----------------------------------------
// Ws[l][n][k] = fp16(W2p[k][n]) where W2p cols 0..2047 from W2, 2048..2111 from b2
__global__ void k_wsplit(const float* __restrict__ W2, const float* __restrict__ b2,
                         __half* __restrict__ Ws, int lo0, int hi0) {
    int idx = lo0 + blockIdx.x * blockDim.x + threadIdx.x;
    if (idx >= hi0) return;
    int k = idx & 63;
    int n = (idx >> 6) % QCOLS;
    int l = idx / (QCOLS * HID);
    float v;
    if (n < 2048) {
        int j = n >> 6, o = n & 63;
        v = W2[(size_t)(l * 32 + j) * 4096 + k * 64 + o];
    } else {
        v = b2[(size_t)l * 4096 + k * 64 + (n - 2048)];
    }
    Ws[idx] = __float2half_rn(v);
}

__device__ __forceinline__ void write_split(__half* hs, int node, int k, float v) {
    __half hi = __float2half_rn(v);
    __half lo = __float2half_rn(v - __half2float(hi));
    __half* r = hs + (size_t)node * KA;
    r[k] = hi;
    r[64 + k] = lo;
}

// h0 = x @ Wp + bp  (+ fp16 split of h0)
__global__ void k_proj(const float* __restrict__ x, const float* __restrict__ Wp,
                       const float* __restrict__ bp, float* __restrict__ h,
                       __half* __restrict__ hs, int N) {
    int t = blockIdx.x * blockDim.x + threadIdx.x;
    if (t >= N * HID) return;
    int n = t >> 6, c = t & 63;
    const float* xr = x + n * 8;
    float acc = bp[c];
#pragma unroll
    for (int k = 0; k < 8; k++) acc += xr[k] * Wp[k * 64 + c];
    h[t] = acc;
    write_split(hs, n, c, acc);
}

// ---------------- WMMA fp16 GEMM: Q = (h_hi+h_lo)(15360x64) @ W^T(64x2112) ---
// block: 128 M x (2 x 96) N subtiles; A smem tile reused across subtiles.
// 8 warps (4m x 2n), warp tile 32x48. fp16 output.
__global__ __launch_bounds__(256) void k_qwmma(const __half* __restrict__ A,
                                               const __half* __restrict__ B,
                                               __half* __restrict__ Q) {
    extern __shared__ __half sm[];
    __half* As = sm;                          // 128 x APAD
    __half* Bs = sm + 128 * APAD;             // 2 x (96 x BPAD)
    float* stage = (float*)(sm + 128 * APAD + 2 * 96 * BPAD);  // 8 x 320 floats
    const int m0 = blockIdx.y * 128;
    const int n0 = blockIdx.x * 192;
    const int t = threadIdx.x;

    // stage A tile: 128 rows x 128 halfs (16 uint4/row)
    for (int i = t; i < 128 * 16; i += 256) {
        int r = i >> 4, c = (i & 15) * 8;
        *(uint4*)(As + r * APAD + c) = *(const uint4*)(A + (size_t)(m0 + r) * KA + c);
    }
    // stage both B subtiles: 2 x 96 rows x 64 halfs (8 uint4/row)
    for (int i = t; i < 2 * 96 * 8; i += 256) {
        int s = i / 768;
        int r = (i % 768) >> 3, c = (i & 7) * 8;
        *(uint4*)(Bs + s * 96 * BPAD + r * BPAD + c) =
            *(const uint4*)(B + (size_t)(n0 + s * 96 + r) * HID + c);
    }
    __syncthreads();

    const int w = t >> 5;
    const int lane = t & 31;
    const int mw = (w & 3) * 32;
    const int nw = (w >> 2) * 48;
    float* wstage = stage + w * 320;  // 16x20 floats per warp

#pragma unroll
    for (int s = 0; s < 2; s++) {
        const __half* Bsub = Bs + s * 96 * BPAD;
        wmma::fragment<wmma::accumulator, 16, 16, 16, float> acc[2][3];
#pragma unroll
        for (int i = 0; i < 2; i++)
#pragma unroll
            for (int j = 0; j < 3; j++) wmma::fill_fragment(acc[i][j], 0.f);

#pragma unroll
        for (int kk = 0; kk < 4; kk++) {
            wmma::fragment<wmma::matrix_b, 16, 16, 16, __half, wmma::col_major> bf[3];
#pragma unroll
            for (int j = 0; j < 3; j++)
                wmma::load_matrix_sync(bf[j], Bsub + (nw + j * 16) * BPAD + kk * 16, BPAD);
#pragma unroll
            for (int pass = 0; pass < 2; pass++) {
                wmma::fragment<wmma::matrix_a, 16, 16, 16, __half, wmma::row_major> af[2];
#pragma unroll
                for (int i = 0; i < 2; i++)
                    wmma::load_matrix_sync(af[i], As + (mw + i * 16) * APAD + pass * 64 + kk * 16, APAD);
#pragma unroll
                for (int i = 0; i < 2; i++)
#pragma unroll
                    for (int j = 0; j < 3; j++)
                        wmma::mma_sync(acc[i][j], af[i], bf[j], acc[i][j]);
            }
        }

        // epilogue: per-warp fp32 stage (stride 20 floats = 80B), fp16 store
#pragma unroll
        for (int i = 0; i < 2; i++) {
#pragma unroll
            for (int j = 0; j < 3; j++) {
                wmma::store_matrix_sync(wstage, acc[i][j], 20, wmma::mem_row_major);
                __syncwarp();
                int r = lane >> 1, c0 = (lane & 1) * 8;
                const float* sr = wstage + r * 20 + c0;
                half2 hv[4];
#pragma unroll
                for (int q = 0; q < 4; q++)
                    hv[q] = __floats2half2_rn(sr[2 * q], sr[2 * q + 1]);
                *(uint4*)(Q + (size_t)(m0 + mw + i * 16 + r) * QCOLS +
                          n0 + s * 96 + nw + j * 16 + c0) = *(uint4*)hv;
                __syncwarp();
            }
        }
    }
}

// ---------------- fused per-graph layer kernel --------------------------------
__global__ __launch_bounds__(256) void k_fused(
    const float* __restrict__ h, const int* __restrict__ src, const int* __restrict__ dst,
    const __half* __restrict__ Qh, const float* __restrict__ W1l, const float* __restrict__ b1l,
    const float* __restrict__ Wr, const float* __restrict__ br,
    const float* __restrict__ gamma, const float* __restrict__ beta,
    const float* __restrict__ rmean, const float* __restrict__ rvar,
    float* __restrict__ hout, __half* __restrict__ hs, int E2) {
    __shared__ float sh[NPG * HID];        // 7.5 KB
    __shared__ float sW[128 * 32];         // 16 KB (W1, later reused for Wr)
    __shared__ float sz[NEPG * 32];        // 10.25 KB
    __shared__ float sagg[NPG * HID];      // 7.5 KB
    __shared__ float sdeg[NPG];
    __shared__ int sse[NEPG], sde[NEPG];

    const int g = blockIdx.x;
    const int tid = threadIdx.x;
    const int w = tid >> 5;
    const int lane = tid & 31;
    const int nbase = g * NPG;

    for (int i = tid; i < NPG * HID; i += 256) {
        sh[i] = h[nbase * HID + i];
        sagg[i] = 0.f;
    }
    for (int i = tid; i < 128 * 32; i += 256) sW[i] = W1l[i];
    if (tid < NPG) sdeg[tid] = 0.f;
    __syncthreads();

    // --- z + deg; warp per edge ---
    float b1v = b1l[lane];
    for (int k = w; k < NEPG; k += 8) {
        int ei = (k < NBR) ? g * NBR + k : E2 + g * NBR + (k - NBR);
        int s = src[ei] - nbase;
        int d = dst[ei] - nbase;
        if (lane == 0) { sse[k] = s; sde[k] = d; atomicAdd(&sdeg[d], 1.0f); }
        const float* hsrow = sh + s * 64;
        const float* hdrow = sh + d * 64;
        float acc = b1v;
#pragma unroll
        for (int kk = 0; kk < 64; kk++) acc += hsrow[kk] * sW[kk * 32 + lane];
#pragma unroll
        for (int kk = 0; kk < 64; kk++) acc += hdrow[kk] * sW[(64 + kk) * 32 + lane];
        sz[k * 32 + lane] = fmaxf(acc, 0.f);
    }
    __syncthreads();

    // --- msg: warp per edge; lane = (j-offset, o-chunk); uint4 fp16 loads ---
    const int c = lane & 7;    // o-chunk: outputs c*8 .. c*8+7
    const int jo = lane >> 3;  // j offset within group of 4
    for (int k = w; k < NEPG; k += 8) {
        int s = sse[k], d = sde[k];
        const __half* Qs = Qh + (size_t)(nbase + s) * QCOLS;
        float zval = sz[k * 32 + lane];
        float acc[8];
#pragma unroll
        for (int i = 0; i < 8; i++) acc[i] = 0.f;
#pragma unroll
        for (int j0 = 0; j0 < 8; j0++) {
            int j = j0 * 4 + jo;
            float zz = __shfl_sync(0xffffffffu, zval, j);
            uint4 qv = *(const uint4*)(Qs + j * 64 + c * 8);
            const half2* qh = (const half2*)&qv;
#pragma unroll
            for (int i = 0; i < 4; i++) {
                float2 f = __half22float2(qh[i]);
                acc[2 * i] += zz * f.x;
                acc[2 * i + 1] += zz * f.y;
            }
        }
#pragma unroll
        for (int i = 0; i < 8; i++) {
            acc[i] += __shfl_xor_sync(0xffffffffu, acc[i], 8);
            acc[i] += __shfl_xor_sync(0xffffffffu, acc[i], 16);
        }
        int o = c * 8 + jo * 2;
        float2 bias = __half22float2(*(const half2*)(Qs + 2048 + o));
        atomicAdd(&sagg[d * 64 + o], acc[jo * 2] + bias.x);
        atomicAdd(&sagg[d * 64 + o + 1], acc[jo * 2 + 1] + bias.y);
    }
    __syncthreads();

    // --- reload sW with Wr ---
    for (int i = tid; i < 64 * 64; i += 256) sW[i] = Wr[i];
    __syncthreads();

    // --- node update ---
    for (int i = tid; i < NPG * HID; i += 256) {
        int n = i >> 6, cc = i & 63;
        const float* hr = sh + n * 64;
        float acc = br[cc];
#pragma unroll
        for (int kk = 0; kk < 64; kk++) acc += hr[kk] * sW[kk * 64 + cc];
        float h2 = sagg[i] / fmaxf(sdeg[n], 1.0f) + acc;
        float scale = gamma[cc] * rsqrtf(rvar[cc] + BN_EPS);
        h2 = (h2 - rmean[cc]) * scale + beta[cc];
        float r = fmaxf(h2, 0.f) + sh[i];
        hout[nbase * HID + i] = r;
        write_split(hs, nbase + n, cc, r);
    }
}

// out[i] = relu([h[u]|h[v]] @ Wm1 + bm1) @ Wm2 + bm2 ; one warp per output row
__global__ void k_final(const float* __restrict__ h, const int* __restrict__ bu,
                        const int* __restrict__ bv, const float* __restrict__ Wm1,
                        const float* __restrict__ bm1, const float* __restrict__ Wm2,
                        const float* __restrict__ bm2, float* __restrict__ out,
                        int nout, int B, int npg) {
    int i = (blockIdx.x * blockDim.x + threadIdx.x) >> 5;
    int lane = threadIdx.x & 31;
    if (i >= nout) return;
    int g = i / B, b = i - g * B;
    int u = bu[b] + g * npg;
    int v = bv[b] + g * npg;
    const float* hu = h + (size_t)u * 64;
    const float* hv = h + (size_t)v * 64;
    float a0 = bm1[lane], a1 = bm1[lane + 32];
#pragma unroll
    for (int k = 0; k < 64; k++) {
        float x0 = hu[k];
        a0 += x0 * Wm1[k * 64 + lane];
        a1 += x0 * Wm1[k * 64 + lane + 32];
    }
#pragma unroll
    for (int k = 0; k < 64; k++) {
        float x1 = hv[k];
        a0 += x1 * Wm1[(64 + k) * 64 + lane];
        a1 += x1 * Wm1[(64 + k) * 64 + lane + 32];
    }
    float r = fmaxf(a0, 0.f) * Wm2[lane] + fmaxf(a1, 0.f) * Wm2[lane + 32];
#pragma unroll
    for (int off = 16; off; off >>= 1) r += __shfl_down_sync(0xffffffffu, r, off);
    if (lane == 0) out[i] = r + bm2[0];
}

extern "C" void kernel_launch(void* const* d_in, const int* in_sizes, int n_in,
                              void* d_out, int out_size) {
    const float* x   = (const float*)d_in[0];
    const int* eidx  = (const int*)d_in[1];
    const int* bu    = (const int*)d_in[2];
    const int* bv    = (const int*)d_in[3];
    int base = (in_sizes[4] == 1) ? 5 : 4;
    const float* Wp    = (const float*)d_in[base + 0];
    const float* bp    = (const float*)d_in[base + 1];
    const float* W1    = (const float*)d_in[base + 2];
    const float* b1    = (const float*)d_in[base + 3];
    const float* W2    = (const float*)d_in[base + 4];
    const float* b2    = (const float*)d_in[base + 5];
    const float* Wr    = (const float*)d_in[base + 6];
    const float* br    = (const float*)d_in[base + 7];
    const float* gamma = (const float*)d_in[base + 8];
    const float* beta  = (const float*)d_in[base + 9];
    const float* rmean = (const float*)d_in[base + 10];
    const float* rvar  = (const float*)d_in[base + 11];
    const float* Wm1   = (const float*)d_in[base + 12];
    const float* bm1   = (const float*)d_in[base + 13];
    const float* Wm2   = (const float*)d_in[base + 14];
    const float* bm2   = (const float*)d_in[base + 15];

    const int Nn = in_sizes[0] / 8;     // 15360
    const int E  = in_sizes[1] / 2;     // 41984
    const int B  = in_sizes[2];         // 41
    const int G  = out_size / B;        // 512
    const int npg = Nn / G;             // 30
    const int* src = eidx;
    const int* dst = eidx + E;
    const int E2 = E / 2;

    static float *p_h0 = nullptr, *p_h1;
    static __half *p_Q, *p_hs, *p_Ws;
    static const int SMEMB = (128 * APAD + 2 * 96 * BPAD) * sizeof(__half) +
                             8 * 320 * sizeof(float);
    if (!p_h0) {
        cudaGetSymbolAddress((void**)&p_h0, g_h0);
        cudaGetSymbolAddress((void**)&p_h1, g_h1);
        cudaGetSymbolAddress((void**)&p_Q, g_Q);
        cudaGetSymbolAddress((void**)&p_hs, g_hs);
        cudaGetSymbolAddress((void**)&p_Ws, g_Ws);
        cudaFuncSetAttribute(k_qwmma, cudaFuncAttributeMaxDynamicSharedMemorySize, SMEMB);
    }

    // prep — ordered so ncu -s 5 lands on k_qwmma (layer 1)
    const int WTOT = NLAYERS * QCOLS * HID;
    k_proj<<<(Nn * HID + 255) / 256, 256>>>(x, Wp, bp, p_h0, p_hs, Nn);
    k_wsplit<<<(WTOT / 2 + 255) / 256, 256>>>(W2, b2, p_Ws, 0, WTOT / 2);
    k_wsplit<<<(WTOT / 2 + 255) / 256, 256>>>(W2, b2, p_Ws, WTOT / 2, WTOT);

    float* cur = p_h0;
    float* nxt = p_h1;
    dim3 gq(QCOLS / 192, Nn / 128);
    for (int l = 0; l < NLAYERS; l++) {
        k_qwmma<<<gq, 256, SMEMB>>>(p_hs, p_Ws + (size_t)l * QCOLS * HID, p_Q);
        k_fused<<<G, 256>>>(cur, src, dst, p_Q,
                            W1 + (size_t)l * 128 * 32, b1 + (size_t)l * 32,
                            Wr + (size_t)l * 64 * 64, br + (size_t)l * 64,
                            gamma + (size_t)l * 64, beta + (size_t)l * 64,
                            rmean + (size_t)l * 64, rvar + (size_t)l * 64,
                            nxt, p_hs, E2);
        float* tmp = cur; cur = nxt; nxt = tmp;
    }
    k_final<<<(out_size + 7) / 8, 256>>>(cur, bu, bv, Wm1, bm1, Wm2, bm2,
                                         (float*)d_out, out_size, B, npg);
}

// round 8
// speedup vs baseline: 1.8441x; 1.0675x over previous
#include <cuda_runtime.h>
#include <cuda_fp16.h>
#include <mma.h>
#include <cstdint>

using namespace nvcuda;

// Problem constants (shapes fixed by the reference)
#define NNODES 15360       // 512 graphs * 30 nodes
#define HID 64
#define NPG 30             // nodes per graph
#define NBR 41             // branches per graph
#define NEPG 82            // edges per graph (bidirectional)
#define NLAYERS 5
#define QCOLS 2112         // 32*64 (w-part) + 64 (b2-part)
#define APAD 72            // padded smem stride for A (halfs)
#define BPAD 72            // padded smem stride for B (halfs)
#define FTHREADS 512       // k_fused block size
#define BN_EPS 1e-5f

// ---------------- scratch (device globals; no allocation allowed) -----------
__device__ float g_h0[NNODES * HID];
__device__ float g_h1[NNODES * HID];
__device__ __half g_Q[(size_t)NNODES * QCOLS];              // ~65 MB fp16
__device__ __half g_hs[(size_t)NNODES * HID];               // fp16 h
__device__ __half g_Ws[(size_t)NLAYERS * QCOLS * HID];      // B  [l][n][64] fp16

// ---------------- prep kernels ----------------------------------------------
// Ws[l][n][k] = fp16(W2p[k][n]) where W2p cols 0..2047 from W2, 2048..2111 from b2
__global__ void k_wsplit(const float* __restrict__ W2, const float* __restrict__ b2,
                         __half* __restrict__ Ws) {
    int idx = blockIdx.x * blockDim.x + threadIdx.x;
    const int total = NLAYERS * QCOLS * HID;
    if (idx >= total) return;
    int k = idx & 63;
    int n = (idx >> 6) % QCOLS;
    int l = idx / (QCOLS * HID);
    float v;
    if (n < 2048) {
        int j = n >> 6, o = n & 63;
        v = W2[(size_t)(l * 32 + j) * 4096 + k * 64 + o];
    } else {
        v = b2[(size_t)l * 4096 + k * 64 + (n - 2048)];
    }
    Ws[idx] = __float2half_rn(v);
}

// h0 = x @ Wp + bp  (+ fp16 copy of h0)
__global__ void k_proj(const float* __restrict__ x, const float* __restrict__ Wp,
                       const float* __restrict__ bp, float* __restrict__ h,
                       __half* __restrict__ hs, int N) {
    int t = blockIdx.x * blockDim.x + threadIdx.x;
    if (t >= N * HID) return;
    int n = t >> 6, c = t & 63;
    const float* xr = x + n * 8;
    float acc = bp[c];
#pragma unroll
    for (int k = 0; k < 8; k++) acc += xr[k] * Wp[k * 64 + c];
    h[t] = acc;
    hs[t] = __float2half_rn(acc);
}

// ---------------- WMMA fp16 GEMM: Q = h(15360x64) @ W^T(64x2112) -------------
// block: 128 M x (2 x 96) N subtiles; A smem tile reused across subtiles.
// 8 warps (4m x 2n), warp tile 32x48. fp16 output.
__global__ __launch_bounds__(256) void k_qwmma(const __half* __restrict__ A,
                                               const __half* __restrict__ B,
                                               __half* __restrict__ Q) {
    extern __shared__ __half sm[];
    __half* As = sm;                          // 128 x APAD
    __half* Bs = sm + 128 * APAD;             // 2 x (96 x BPAD)
    float* stage = (float*)(sm + 128 * APAD + 2 * 96 * BPAD);  // 8 x 320 floats
    const int m0 = blockIdx.y * 128;
    const int n0 = blockIdx.x * 192;
    const int t = threadIdx.x;

    // stage A tile: 128 rows x 64 halfs (8 uint4/row)
    for (int i = t; i < 128 * 8; i += 256) {
        int r = i >> 3, c = (i & 7) * 8;
        *(uint4*)(As + r * APAD + c) = *(const uint4*)(A + (size_t)(m0 + r) * HID + c);
    }
    // stage both B subtiles: 2 x 96 rows x 64 halfs (8 uint4/row)
    for (int i = t; i < 2 * 96 * 8; i += 256) {
        int s = i / 768;
        int r = (i % 768) >> 3, c = (i & 7) * 8;
        *(uint4*)(Bs + s * 96 * BPAD + r * BPAD + c) =
            *(const uint4*)(B + (size_t)(n0 + s * 96 + r) * HID + c);
    }
    __syncthreads();

    const int w = t >> 5;
    const int lane = t & 31;
    const int mw = (w & 3) * 32;
    const int nw = (w >> 2) * 48;
    float* wstage = stage + w * 320;  // 16x20 floats per warp

#pragma unroll
    for (int s = 0; s < 2; s++) {
        const __half* Bsub = Bs + s * 96 * BPAD;
        wmma::fragment<wmma::accumulator, 16, 16, 16, float> acc[2][3];
#pragma unroll
        for (int i = 0; i < 2; i++)
#pragma unroll
            for (int j = 0; j < 3; j++) wmma::fill_fragment(acc[i][j], 0.f);

#pragma unroll
        for (int kk = 0; kk < 4; kk++) {
            wmma::fragment<wmma::matrix_b, 16, 16, 16, __half, wmma::col_major> bf[3];
#pragma unroll
            for (int j = 0; j < 3; j++)
                wmma::load_matrix_sync(bf[j], Bsub + (nw + j * 16) * BPAD + kk * 16, BPAD);
            wmma::fragment<wmma::matrix_a, 16, 16, 16, __half, wmma::row_major> af[2];
#pragma unroll
            for (int i = 0; i < 2; i++)
                wmma::load_matrix_sync(af[i], As + (mw + i * 16) * APAD + kk * 16, APAD);
#pragma unroll
            for (int i = 0; i < 2; i++)
#pragma unroll
                for (int j = 0; j < 3; j++)
                    wmma::mma_sync(acc[i][j], af[i], bf[j], acc[i][j]);
        }

        // epilogue: per-warp fp32 stage (stride 20 floats = 80B), fp16 store
#pragma unroll
        for (int i = 0; i < 2; i++) {
#pragma unroll
            for (int j = 0; j < 3; j++) {
                wmma::store_matrix_sync(wstage, acc[i][j], 20, wmma::mem_row_major);
                __syncwarp();
                int r = lane >> 1, c0 = (lane & 1) * 8;
                const float* sr = wstage + r * 20 + c0;
                half2 hv[4];
#pragma unroll
                for (int q = 0; q < 4; q++)
                    hv[q] = __floats2half2_rn(sr[2 * q], sr[2 * q + 1]);
                *(uint4*)(Q + (size_t)(m0 + mw + i * 16 + r) * QCOLS +
                          n0 + s * 96 + nw + j * 16 + c0) = *(uint4*)hv;
                __syncwarp();
            }
        }
    }
}

// ---------------- fused per-graph layer kernel --------------------------------
__global__ __launch_bounds__(FTHREADS) void k_fused(
    const float* __restrict__ h, const int* __restrict__ src, const int* __restrict__ dst,
    const __half* __restrict__ Qh, const float* __restrict__ W1l, const float* __restrict__ b1l,
    const float* __restrict__ Wr, const float* __restrict__ br,
    const float* __restrict__ gamma, const float* __restrict__ beta,
    const float* __restrict__ rmean, const float* __restrict__ rvar,
    float* __restrict__ hout, __half* __restrict__ hs, int E2) {
    __shared__ float sh[NPG * HID];        // 7.5 KB
    __shared__ float sW[128 * 32];         // 16 KB (W1, later reused for Wr)
    __shared__ float sz[NEPG * 32];        // 10.25 KB
    __shared__ float sagg[NPG * HID];      // 7.5 KB
    __shared__ float sdeg[NPG];
    __shared__ int sse[NEPG], sde[NEPG];

    const int g = blockIdx.x;
    const int tid = threadIdx.x;
    const int w = tid >> 5;
    const int lane = tid & 31;
    const int nbase = g * NPG;

    for (int i = tid; i < NPG * HID; i += FTHREADS) {
        sh[i] = h[nbase * HID + i];
        sagg[i] = 0.f;
    }
    for (int i = tid; i < 128 * 32; i += FTHREADS) sW[i] = W1l[i];
    if (tid < NPG) sdeg[tid] = 0.f;
    __syncthreads();

    // --- z + deg; warp per edge ---
    float b1v = b1l[lane];
    for (int k = w; k < NEPG; k += FTHREADS / 32) {
        int ei = (k < NBR) ? g * NBR + k : E2 + g * NBR + (k - NBR);
        int s = src[ei] - nbase;
        int d = dst[ei] - nbase;
        if (lane == 0) { sse[k] = s; sde[k] = d; atomicAdd(&sdeg[d], 1.0f); }
        const float* hsrow = sh + s * 64;
        const float* hdrow = sh + d * 64;
        float acc = b1v;
#pragma unroll
        for (int kk = 0; kk < 64; kk++) acc += hsrow[kk] * sW[kk * 32 + lane];
#pragma unroll
        for (int kk = 0; kk < 64; kk++) acc += hdrow[kk] * sW[(64 + kk) * 32 + lane];
        sz[k * 32 + lane] = fmaxf(acc, 0.f);
    }
    __syncthreads();

    // --- msg: warp per edge; lane = (j-offset, o-chunk); uint4 fp16 loads ---
    const int c = lane & 7;    // o-chunk: outputs c*8 .. c*8+7
    const int jo = lane >> 3;  // j offset within group of 4
    for (int k = w; k < NEPG; k += FTHREADS / 32) {
        int s = sse[k], d = sde[k];
        const __half* Qs = Qh + (size_t)(nbase + s) * QCOLS;
        float zval = sz[k * 32 + lane];
        float acc[8];
#pragma unroll
        for (int i = 0; i < 8; i++) acc[i] = 0.f;
#pragma unroll
        for (int j0 = 0; j0 < 8; j0++) {
            int j = j0 * 4 + jo;
            float zz = __shfl_sync(0xffffffffu, zval, j);
            uint4 qv = *(const uint4*)(Qs + j * 64 + c * 8);
            const half2* qh = (const half2*)&qv;
#pragma unroll
            for (int i = 0; i < 4; i++) {
                float2 f = __half22float2(qh[i]);
                acc[2 * i] += zz * f.x;
                acc[2 * i + 1] += zz * f.y;
            }
        }
#pragma unroll
        for (int i = 0; i < 8; i++) {
            acc[i] += __shfl_xor_sync(0xffffffffu, acc[i], 8);
            acc[i] += __shfl_xor_sync(0xffffffffu, acc[i], 16);
        }
        int o = c * 8 + jo * 2;
        float2 bias = __half22float2(*(const half2*)(Qs + 2048 + o));
        atomicAdd(&sagg[d * 64 + o], acc[jo * 2] + bias.x);
        atomicAdd(&sagg[d * 64 + o + 1], acc[jo * 2 + 1] + bias.y);
    }
    __syncthreads();

    // --- reload sW with Wr ---
    for (int i = tid; i < 64 * 64; i += FTHREADS) sW[i] = Wr[i];
    __syncthreads();

    // --- node update ---
    for (int i = tid; i < NPG * HID; i += FTHREADS) {
        int n = i >> 6, cc = i & 63;
        const float* hr = sh + n * 64;
        float acc = br[cc];
#pragma unroll
        for (int kk = 0; kk < 64; kk++) acc += hr[kk] * sW[kk * 64 + cc];
        float h2 = sagg[i] / fmaxf(sdeg[n], 1.0f) + acc;
        float scale = gamma[cc] * rsqrtf(rvar[cc] + BN_EPS);
        h2 = (h2 - rmean[cc]) * scale + beta[cc];
        float r = fmaxf(h2, 0.f) + sh[i];
        hout[nbase * HID + i] = r;
        hs[nbase * HID + i] = __float2half_rn(r);
    }
}

// out[i] = relu([h[u]|h[v]] @ Wm1 + bm1) @ Wm2 + bm2 ; one warp per output row
__global__ void k_final(const float* __restrict__ h, const int* __restrict__ bu,
                        const int* __restrict__ bv, const float* __restrict__ Wm1,
                        const float* __restrict__ bm1, const float* __restrict__ Wm2,
                        const float* __restrict__ bm2, float* __restrict__ out,
                        int nout, int B, int npg) {
    int i = (blockIdx.x * blockDim.x + threadIdx.x) >> 5;
    int lane = threadIdx.x & 31;
    if (i >= nout) return;
    int g = i / B, b = i - g * B;
    int u = bu[b] + g * npg;
    int v = bv[b] + g * npg;
    const float* hu = h + (size_t)u * 64;
    const float* hv = h + (size_t)v * 64;
    float a0 = bm1[lane], a1 = bm1[lane + 32];
#pragma unroll
    for (int k = 0; k < 64; k++) {
        float x0 = hu[k];
        a0 += x0 * Wm1[k * 64 + lane];
        a1 += x0 * Wm1[k * 64 + lane + 32];
    }
#pragma unroll
    for (int k = 0; k < 64; k++) {
        float x1 = hv[k];
        a0 += x1 * Wm1[(64 + k) * 64 + lane];
        a1 += x1 * Wm1[(64 + k) * 64 + lane + 32];
    }
    float r = fmaxf(a0, 0.f) * Wm2[lane] + fmaxf(a1, 0.f) * Wm2[lane + 32];
#pragma unroll
    for (int off = 16; off; off >>= 1) r += __shfl_down_sync(0xffffffffu, r, off);
    if (lane == 0) out[i] = r + bm2[0];
}

extern "C" void kernel_launch(void* const* d_in, const int* in_sizes, int n_in,
                              void* d_out, int out_size) {
    const float* x   = (const float*)d_in[0];
    const int* eidx  = (const int*)d_in[1];
    const int* bu    = (const int*)d_in[2];
    const int* bv    = (const int*)d_in[3];
    int base = (in_sizes[4] == 1) ? 5 : 4;
    const float* Wp    = (const float*)d_in[base + 0];
    const float* bp    = (const float*)d_in[base + 1];
    const float* W1    = (const float*)d_in[base + 2];
    const float* b1    = (const float*)d_in[base + 3];
    const float* W2    = (const float*)d_in[base + 4];
    const float* b2    = (const float*)d_in[base + 5];
    const float* Wr    = (const float*)d_in[base + 6];
    const float* br    = (const float*)d_in[base + 7];
    const float* gamma = (const float*)d_in[base + 8];
    const float* beta  = (const float*)d_in[base + 9];
    const float* rmean = (const float*)d_in[base + 10];
    const float* rvar  = (const float*)d_in[base + 11];
    const float* Wm1   = (const float*)d_in[base + 12];
    const float* bm1   = (const float*)d_in[base + 13];
    const float* Wm2   = (const float*)d_in[base + 14];
    const float* bm2   = (const float*)d_in[base + 15];

    const int Nn = in_sizes[0] / 8;     // 15360
    const int E  = in_sizes[1] / 2;     // 41984
    const int B  = in_sizes[2];         // 41
    const int G  = out_size / B;        // 512
    const int npg = Nn / G;             // 30
    const int* src = eidx;
    const int* dst = eidx + E;
    const int E2 = E / 2;

    static float *p_h0 = nullptr, *p_h1;
    static __half *p_Q, *p_hs, *p_Ws;
    static const int SMEMB = (128 * APAD + 2 * 96 * BPAD) * sizeof(__half) +
                             8 * 320 * sizeof(float);
    if (!p_h0) {
        cudaGetSymbolAddress((void**)&p_h0, g_h0);
        cudaGetSymbolAddress((void**)&p_h1, g_h1);
        cudaGetSymbolAddress((void**)&p_Q, g_Q);
        cudaGetSymbolAddress((void**)&p_hs, g_hs);
        cudaGetSymbolAddress((void**)&p_Ws, g_Ws);
        cudaFuncSetAttribute(k_qwmma, cudaFuncAttributeMaxDynamicSharedMemorySize, SMEMB);
    }

    // launches: 0=proj, 1=wsplit, 2=qwmma(l0), 3=fused(l0), 4=qwmma(l1),
    // 5=fused(l1) <- ncu -s 5 profiles k_fused
    const int WTOT = NLAYERS * QCOLS * HID;
    k_proj<<<(Nn * HID + 255) / 256, 256>>>(x, Wp, bp, p_h0, p_hs, Nn);
    k_wsplit<<<(WTOT + 255) / 256, 256>>>(W2, b2, p_Ws);

    float* cur = p_h0;
    float* nxt = p_h1;
    dim3 gq(QCOLS / 192, Nn / 128);
    for (int l = 0; l < NLAYERS; l++) {
        k_qwmma<<<gq, 256, SMEMB>>>(p_hs, p_Ws + (size_t)l * QCOLS * HID, p_Q);
        k_fused<<<G, FTHREADS>>>(cur, src, dst, p_Q,
                            W1 + (size_t)l * 128 * 32, b1 + (size_t)l * 32,
                            Wr + (size_t)l * 64 * 64, br + (size_t)l * 64,
                            gamma + (size_t)l * 64, beta + (size_t)l * 64,
                            rmean + (size_t)l * 64, rvar + (size_t)l * 64,
                            nxt, p_hs, E2);
        float* tmp = cur; cur = nxt; nxt = tmp;
    }
    k_final<<<(out_size + 7) / 8, 256>>>(cur, bu, bv, Wm1, bm1, Wm2, bm2,
                                         (float*)d_out, out_size, B, npg);
}

// round 9
// speedup vs baseline: 2.3432x; 1.2706x over previous
#include <cuda_runtime.h>
#include <cuda_fp16.h>
#include <mma.h>
#include <cstdint>

using namespace nvcuda;

// Problem constants (shapes fixed by the reference)
#define NNODES 15360       // 512 graphs * 30 nodes
#define HID 64
#define NPG 30             // nodes per graph
#define NBR 41             // branches per graph
#define NEPG 82            // edges per graph (bidirectional)
#define NLAYERS 5
#define QCOLS 2112         // 32*64 (w-part) + 64 (b2-part)
#define APAD 72            // padded smem stride for A (halfs)
#define BPAD 72            // padded smem stride for B (halfs)
#define FTHREADS 512       // k_fused block size
#define BN_EPS 1e-5f

// k_fused dynamic smem layout (bytes)
#define F_SH    0                    // float[1920]  h tile
#define F_SAGG  7680                 // float[1920]  agg
#define F_SZ    15360                // float[96*32] z
#define F_EA    27648                // half[96*136] ea  (reused: float Wr[4096])
#define F_W1H   53760                // half[128*40] W1 fp16
#define F_SDEG  64000                // float[30]
#define F_SSE   64120                // int[82]
#define F_SDE   64448                // int[82]
#define F_TOT   64776

// ---------------- scratch (device globals; no allocation allowed) -----------
__device__ float g_h0[NNODES * HID];
__device__ float g_h1[NNODES * HID];
__device__ __half g_Q[(size_t)NNODES * QCOLS];              // ~65 MB fp16
__device__ __half g_hs[(size_t)NNODES * HID];               // fp16 h
__device__ __half g_Ws[(size_t)NLAYERS * QCOLS * HID];      // B  [l][n][64] fp16

// ---------------- prep kernels ----------------------------------------------
__global__ void k_wsplit(const float* __restrict__ W2, const float* __restrict__ b2,
                         __half* __restrict__ Ws) {
    int idx = blockIdx.x * blockDim.x + threadIdx.x;
    const int total = NLAYERS * QCOLS * HID;
    if (idx >= total) return;
    int k = idx & 63;
    int n = (idx >> 6) % QCOLS;
    int l = idx / (QCOLS * HID);
    float v;
    if (n < 2048) {
        int j = n >> 6, o = n & 63;
        v = W2[(size_t)(l * 32 + j) * 4096 + k * 64 + o];
    } else {
        v = b2[(size_t)l * 4096 + k * 64 + (n - 2048)];
    }
    Ws[idx] = __float2half_rn(v);
}

// h0 = x @ Wp + bp  (+ fp16 copy of h0)
__global__ void k_proj(const float* __restrict__ x, const float* __restrict__ Wp,
                       const float* __restrict__ bp, float* __restrict__ h,
                       __half* __restrict__ hs, int N) {
    int t = blockIdx.x * blockDim.x + threadIdx.x;
    if (t >= N * HID) return;
    int n = t >> 6, c = t & 63;
    const float* xr = x + n * 8;
    float acc = bp[c];
#pragma unroll
    for (int k = 0; k < 8; k++) acc += xr[k] * Wp[k * 64 + c];
    h[t] = acc;
    hs[t] = __float2half_rn(acc);
}

// ---------------- WMMA fp16 GEMM: Q = h(15360x64) @ W^T(64x2112) -------------
__global__ __launch_bounds__(256) void k_qwmma(const __half* __restrict__ A,
                                               const __half* __restrict__ B,
                                               __half* __restrict__ Q) {
    extern __shared__ __half sm[];
    __half* As = sm;                          // 128 x APAD
    __half* Bs = sm + 128 * APAD;             // 2 x (96 x BPAD)
    float* stage = (float*)(sm + 128 * APAD + 2 * 96 * BPAD);  // 8 x 320 floats
    const int m0 = blockIdx.y * 128;
    const int n0 = blockIdx.x * 192;
    const int t = threadIdx.x;

    for (int i = t; i < 128 * 8; i += 256) {
        int r = i >> 3, c = (i & 7) * 8;
        *(uint4*)(As + r * APAD + c) = *(const uint4*)(A + (size_t)(m0 + r) * HID + c);
    }
    for (int i = t; i < 2 * 96 * 8; i += 256) {
        int s = i / 768;
        int r = (i % 768) >> 3, c = (i & 7) * 8;
        *(uint4*)(Bs + s * 96 * BPAD + r * BPAD + c) =
            *(const uint4*)(B + (size_t)(n0 + s * 96 + r) * HID + c);
    }
    __syncthreads();

    const int w = t >> 5;
    const int lane = t & 31;
    const int mw = (w & 3) * 32;
    const int nw = (w >> 2) * 48;
    float* wstage = stage + w * 320;

#pragma unroll
    for (int s = 0; s < 2; s++) {
        const __half* Bsub = Bs + s * 96 * BPAD;
        wmma::fragment<wmma::accumulator, 16, 16, 16, float> acc[2][3];
#pragma unroll
        for (int i = 0; i < 2; i++)
#pragma unroll
            for (int j = 0; j < 3; j++) wmma::fill_fragment(acc[i][j], 0.f);

#pragma unroll
        for (int kk = 0; kk < 4; kk++) {
            wmma::fragment<wmma::matrix_b, 16, 16, 16, __half, wmma::col_major> bf[3];
#pragma unroll
            for (int j = 0; j < 3; j++)
                wmma::load_matrix_sync(bf[j], Bsub + (nw + j * 16) * BPAD + kk * 16, BPAD);
            wmma::fragment<wmma::matrix_a, 16, 16, 16, __half, wmma::row_major> af[2];
#pragma unroll
            for (int i = 0; i < 2; i++)
                wmma::load_matrix_sync(af[i], As + (mw + i * 16) * APAD + kk * 16, APAD);
#pragma unroll
            for (int i = 0; i < 2; i++)
#pragma unroll
                for (int j = 0; j < 3; j++)
                    wmma::mma_sync(acc[i][j], af[i], bf[j], acc[i][j]);
        }

#pragma unroll
        for (int i = 0; i < 2; i++) {
#pragma unroll
            for (int j = 0; j < 3; j++) {
                wmma::store_matrix_sync(wstage, acc[i][j], 20, wmma::mem_row_major);
                __syncwarp();
                int r = lane >> 1, c0 = (lane & 1) * 8;
                const float* sr = wstage + r * 20 + c0;
                half2 hv[4];
#pragma unroll
                for (int q = 0; q < 4; q++)
                    hv[q] = __floats2half2_rn(sr[2 * q], sr[2 * q + 1]);
                *(uint4*)(Q + (size_t)(m0 + mw + i * 16 + r) * QCOLS +
                          n0 + s * 96 + nw + j * 16 + c0) = *(uint4*)hv;
                __syncwarp();
            }
        }
    }
}

// ---------------- fused per-graph layer kernel --------------------------------
// z via WMMA (ea[96,128] @ W1[128,32]), then msg gather, smem scatter, node update
__global__ __launch_bounds__(FTHREADS, 2) void k_fused(
    const float* __restrict__ h, const int* __restrict__ src, const int* __restrict__ dst,
    const __half* __restrict__ Qh, const float* __restrict__ W1l, const float* __restrict__ b1l,
    const float* __restrict__ Wr, const float* __restrict__ br,
    const float* __restrict__ gamma, const float* __restrict__ beta,
    const float* __restrict__ rmean, const float* __restrict__ rvar,
    float* __restrict__ hout, __half* __restrict__ hs, int E2) {
    extern __shared__ char smraw[];
    float* sh   = (float*)(smraw + F_SH);
    float* sagg = (float*)(smraw + F_SAGG);
    float* sz   = (float*)(smraw + F_SZ);
    __half* ea  = (__half*)(smraw + F_EA);
    float* sWr  = (float*)(smraw + F_EA);   // reused after msg phase
    __half* w1h = (__half*)(smraw + F_W1H);
    float* sdeg = (float*)(smraw + F_SDEG);
    int* sse    = (int*)(smraw + F_SSE);
    int* sde    = (int*)(smraw + F_SDE);

    const int g = blockIdx.x;
    const int tid = threadIdx.x;
    const int w = tid >> 5;
    const int lane = tid & 31;
    const int nbase = g * NPG;

    // phase A: load h tile, zero agg, W1->fp16, zero deg
    for (int i = tid; i < NPG * HID; i += FTHREADS) {
        sh[i] = h[nbase * HID + i];
        sagg[i] = 0.f;
    }
    for (int i = tid; i < 128 * 32; i += FTHREADS)
        w1h[(i >> 5) * 40 + (i & 31)] = __float2half_rn(W1l[i]);
    if (tid < NPG) sdeg[tid] = 0.f;
    __syncthreads();

    // phase B: edge indices + degree
    if (tid < NEPG) {
        int k = tid;
        int ei = (k < NBR) ? g * NBR + k : E2 + g * NBR + (k - NBR);
        int s = src[ei] - nbase;
        int d = dst[ei] - nbase;
        sse[k] = s; sde[k] = d;
        atomicAdd(&sdeg[d], 1.0f);
    }
    __syncthreads();

    // phase C: build ea[96][136] fp16 = [h[src] | h[dst]] per edge row
    for (int i = tid; i < 96 * 128; i += FTHREADS) {
        int k = i >> 7, c = i & 127;
        float v = 0.f;
        if (k < NEPG) {
            int node = (c < 64) ? sse[k] : sde[k];
            v = sh[node * 64 + (c & 63)];
        }
        ea[k * 136 + c] = __float2half_rn(v);
    }
    __syncthreads();

    // phase D: z = ea @ W1 via WMMA; 12 warp-tiles (6m x 2n)
    if (w < 12) {
        int mt = w >> 1, nt = w & 1;
        wmma::fragment<wmma::accumulator, 16, 16, 16, float> acc;
        wmma::fill_fragment(acc, 0.f);
#pragma unroll
        for (int kk = 0; kk < 8; kk++) {
            wmma::fragment<wmma::matrix_a, 16, 16, 16, __half, wmma::row_major> af;
            wmma::fragment<wmma::matrix_b, 16, 16, 16, __half, wmma::row_major> bf;
            wmma::load_matrix_sync(af, ea + (mt * 16) * 136 + kk * 16, 136);
            wmma::load_matrix_sync(bf, w1h + (kk * 16) * 40 + nt * 16, 40);
            wmma::mma_sync(acc, af, bf, acc);
        }
        wmma::store_matrix_sync(sz + mt * 16 * 32 + nt * 16, acc, 32, wmma::mem_row_major);
    }
    __syncthreads();

    // phase E: bias + relu on z
    for (int i = tid; i < NEPG * 32; i += FTHREADS)
        sz[i] = fmaxf(sz[i] + b1l[i & 31], 0.f);
    __syncthreads();

    // phase F: msg gather (warp per edge), smem scatter
    const int c = lane & 7;    // o-chunk: outputs c*8 .. c*8+7
    const int jo = lane >> 3;  // j offset within group of 4
    for (int k = w; k < NEPG; k += FTHREADS / 32) {
        int s = sse[k], d = sde[k];
        const __half* Qs = Qh + (size_t)(nbase + s) * QCOLS;
        float zval = sz[k * 32 + lane];
        float acc[8];
#pragma unroll
        for (int i = 0; i < 8; i++) acc[i] = 0.f;
#pragma unroll
        for (int j0 = 0; j0 < 8; j0++) {
            int j = j0 * 4 + jo;
            float zz = __shfl_sync(0xffffffffu, zval, j);
            uint4 qv = *(const uint4*)(Qs + j * 64 + c * 8);
            const half2* qh = (const half2*)&qv;
#pragma unroll
            for (int i = 0; i < 4; i++) {
                float2 f = __half22float2(qh[i]);
                acc[2 * i] += zz * f.x;
                acc[2 * i + 1] += zz * f.y;
            }
        }
#pragma unroll
        for (int i = 0; i < 8; i++) {
            acc[i] += __shfl_xor_sync(0xffffffffu, acc[i], 8);
            acc[i] += __shfl_xor_sync(0xffffffffu, acc[i], 16);
        }
        int o = c * 8 + jo * 2;
        float2 bias = __half22float2(*(const half2*)(Qs + 2048 + o));
        atomicAdd(&sagg[d * 64 + o], acc[jo * 2] + bias.x);
        atomicAdd(&sagg[d * 64 + o + 1], acc[jo * 2 + 1] + bias.y);
    }
    __syncthreads();

    // phase G: load Wr (fp32) into the ea region
    for (int i = tid; i < 64 * 64; i += FTHREADS) sWr[i] = Wr[i];
    __syncthreads();

    // phase H: node update
    for (int i = tid; i < NPG * HID; i += FTHREADS) {
        int n = i >> 6, cc = i & 63;
        const float* hr = sh + n * 64;
        float acc = br[cc];
#pragma unroll
        for (int kk = 0; kk < 64; kk++) acc += hr[kk] * sWr[kk * 64 + cc];
        float h2 = sagg[i] / fmaxf(sdeg[n], 1.0f) + acc;
        float scale = gamma[cc] * rsqrtf(rvar[cc] + BN_EPS);
        h2 = (h2 - rmean[cc]) * scale + beta[cc];
        float r = fmaxf(h2, 0.f) + sh[i];
        hout[nbase * HID + i] = r;
        hs[nbase * HID + i] = __float2half_rn(r);
    }
}

// out[i] = relu([h[u]|h[v]] @ Wm1 + bm1) @ Wm2 + bm2 ; one warp per output row
__global__ void k_final(const float* __restrict__ h, const int* __restrict__ bu,
                        const int* __restrict__ bv, const float* __restrict__ Wm1,
                        const float* __restrict__ bm1, const float* __restrict__ Wm2,
                        const float* __restrict__ bm2, float* __restrict__ out,
                        int nout, int B, int npg) {
    int i = (blockIdx.x * blockDim.x + threadIdx.x) >> 5;
    int lane = threadIdx.x & 31;
    if (i >= nout) return;
    int g = i / B, b = i - g * B;
    int u = bu[b] + g * npg;
    int v = bv[b] + g * npg;
    const float* hu = h + (size_t)u * 64;
    const float* hv = h + (size_t)v * 64;
    float a0 = bm1[lane], a1 = bm1[lane + 32];
#pragma unroll
    for (int k = 0; k < 64; k++) {
        float x0 = hu[k];
        a0 += x0 * Wm1[k * 64 + lane];
        a1 += x0 * Wm1[k * 64 + lane + 32];
    }
#pragma unroll
    for (int k = 0; k < 64; k++) {
        float x1 = hv[k];
        a0 += x1 * Wm1[(64 + k) * 64 + lane];
        a1 += x1 * Wm1[(64 + k) * 64 + lane + 32];
    }
    float r = fmaxf(a0, 0.f) * Wm2[lane] + fmaxf(a1, 0.f) * Wm2[lane + 32];
#pragma unroll
    for (int off = 16; off; off >>= 1) r += __shfl_down_sync(0xffffffffu, r, off);
    if (lane == 0) out[i] = r + bm2[0];
}

extern "C" void kernel_launch(void* const* d_in, const int* in_sizes, int n_in,
                              void* d_out, int out_size) {
    const float* x   = (const float*)d_in[0];
    const int* eidx  = (const int*)d_in[1];
    const int* bu    = (const int*)d_in[2];
    const int* bv    = (const int*)d_in[3];
    int base = (in_sizes[4] == 1) ? 5 : 4;
    const float* Wp    = (const float*)d_in[base + 0];
    const float* bp    = (const float*)d_in[base + 1];
    const float* W1    = (const float*)d_in[base + 2];
    const float* b1    = (const float*)d_in[base + 3];
    const float* W2    = (const float*)d_in[base + 4];
    const float* b2    = (const float*)d_in[base + 5];
    const float* Wr    = (const float*)d_in[base + 6];
    const float* br    = (const float*)d_in[base + 7];
    const float* gamma = (const float*)d_in[base + 8];
    const float* beta  = (const float*)d_in[base + 9];
    const float* rmean = (const float*)d_in[base + 10];
    const float* rvar  = (const float*)d_in[base + 11];
    const float* Wm1   = (const float*)d_in[base + 12];
    const float* bm1   = (const float*)d_in[base + 13];
    const float* Wm2   = (const float*)d_in[base + 14];
    const float* bm2   = (const float*)d_in[base + 15];

    const int Nn = in_sizes[0] / 8;     // 15360
    const int E  = in_sizes[1] / 2;     // 41984
    const int B  = in_sizes[2];         // 41
    const int G  = out_size / B;        // 512
    const int npg = Nn / G;             // 30
    const int* src = eidx;
    const int* dst = eidx + E;
    const int E2 = E / 2;

    static float *p_h0 = nullptr, *p_h1;
    static __half *p_Q, *p_hs, *p_Ws;
    static const int SMEMB = (128 * APAD + 2 * 96 * BPAD) * sizeof(__half) +
                             8 * 320 * sizeof(float);
    if (!p_h0) {
        cudaGetSymbolAddress((void**)&p_h0, g_h0);
        cudaGetSymbolAddress((void**)&p_h1, g_h1);
        cudaGetSymbolAddress((void**)&p_Q, g_Q);
        cudaGetSymbolAddress((void**)&p_hs, g_hs);
        cudaGetSymbolAddress((void**)&p_Ws, g_Ws);
        cudaFuncSetAttribute(k_qwmma, cudaFuncAttributeMaxDynamicSharedMemorySize, SMEMB);
        cudaFuncSetAttribute(k_fused, cudaFuncAttributeMaxDynamicSharedMemorySize, F_TOT);
    }

    // launches: 0=proj, 1=wsplit, 2=qwmma(l0), 3=fused(l0), 4=qwmma(l1),
    // 5=fused(l1) <- ncu -s 5 profiles k_fused
    const int WTOT = NLAYERS * QCOLS * HID;
    k_proj<<<(Nn * HID + 255) / 256, 256>>>(x, Wp, bp, p_h0, p_hs, Nn);
    k_wsplit<<<(WTOT + 255) / 256, 256>>>(W2, b2, p_Ws);

    float* cur = p_h0;
    float* nxt = p_h1;
    dim3 gq(QCOLS / 192, Nn / 128);
    for (int l = 0; l < NLAYERS; l++) {
        k_qwmma<<<gq, 256, SMEMB>>>(p_hs, p_Ws + (size_t)l * QCOLS * HID, p_Q);
        k_fused<<<G, FTHREADS, F_TOT>>>(cur, src, dst, p_Q,
                            W1 + (size_t)l * 128 * 32, b1 + (size_t)l * 32,
                            Wr + (size_t)l * 64 * 64, br + (size_t)l * 64,
                            gamma + (size_t)l * 64, beta + (size_t)l * 64,
                            rmean + (size_t)l * 64, rvar + (size_t)l * 64,
                            nxt, p_hs, E2);
        float* tmp = cur; cur = nxt; nxt = tmp;
    }
    k_final<<<(out_size + 7) / 8, 256>>>(cur, bu, bv, Wm1, bm1, Wm2, bm2,
                                         (float*)d_out, out_size, B, npg);
}